// round 8
// baseline (speedup 1.0000x reference)
#include <cuda_runtime.h>
#include <cuda_bf16.h>
#include <math.h>
#include <stdint.h>

#define D_IN 768
#define H    256
#define NB   64
#define NT   512
#define BT   (NB*NT)    // 32768
#define G3   768        // 3*H
#define NCTA 128        // scan CTAs (single wave)

// ---------------- scratch (static device arrays: allowed) ----------------
__device__ float g_gi1[BT * (size_t)G3];                 // 96 MB, time-major rows (t*64+b)
__device__ float g_gi2[BT * (size_t)G3];                 // 96 MB
__device__ __nv_bfloat16 g_Abuf[BT * (size_t)(3*D_IN)];  // 144 MB [x_hi|x_lo|x_hi] time-major
__device__ __nv_bfloat16 g_A3[BT * (size_t)(3*H)];       // 48 MB  [h_hi|h_lo|h_hi] time-major
__device__ __nv_bfloat16 g_B1[(size_t)G3 * (3*D_IN)];    // W_ih1^T split-stacked
__device__ __nv_bfloat16 g_B2[(size_t)G3 * (3*D_IN)];    // W_ih2[:768]^T split-stacked
__device__ __nv_bfloat16 g_B3[(size_t)G3 * (3*H)];       // W_ih2[768:]^T split-stacked
__device__ float g_hbuf[2][H * NB];                      // TRANSPOSED: [col][b]
__device__ unsigned g_arrive[NCTA];                      // per-CTA barrier flags

// ---------------- helpers ----------------
__device__ __forceinline__ uint32_t smem_u32(const void* p) {
    uint32_t a;
    asm("{ .reg .u64 t; cvta.to.shared.u64 t, %1; cvt.u32.u64 %0, t; }" : "=r"(a) : "l"(p));
    return a;
}
__device__ __forceinline__ void ldsm_x4(uint32_t& r0, uint32_t& r1, uint32_t& r2, uint32_t& r3,
                                        uint32_t addr) {
    asm volatile("ldmatrix.sync.aligned.m8n8.x4.shared.b16 {%0,%1,%2,%3}, [%4];"
                 : "=r"(r0), "=r"(r1), "=r"(r2), "=r"(r3) : "r"(addr));
}
__device__ __forceinline__ void mma_bf16(float* c, const uint32_t* a, const uint32_t* b) {
    asm volatile("mma.sync.aligned.m16n8k16.row.col.f32.bf16.bf16.f32 "
                 "{%0,%1,%2,%3}, {%4,%5,%6,%7}, {%8,%9}, {%0,%1,%2,%3};"
                 : "+f"(c[0]), "+f"(c[1]), "+f"(c[2]), "+f"(c[3])
                 : "r"(a[0]), "r"(a[1]), "r"(a[2]), "r"(a[3]), "r"(b[0]), "r"(b[1]));
}
__device__ __forceinline__ void cp16(uint32_t dst, const void* src) {
    asm volatile("cp.async.cg.shared.global [%0], [%1], 16;" :: "r"(dst), "l"(src));
}
__device__ __forceinline__ void cp_commit() { asm volatile("cp.async.commit_group;"); }
__device__ __forceinline__ void cp_wait1()  { asm volatile("cp.async.wait_group 1;"); }

// swizzled byte offset inside a 128row x 32col bf16 tile (64B rows, 16B chunks)
__device__ __forceinline__ uint32_t sw_off(int row, int c) {
    return ((uint32_t)row << 6) + (((uint32_t)(c ^ ((row >> 1) & 3))) << 4);
}

// ---------------- init ----------------
__global__ void init_kernel() {
    int tid = blockIdx.x * blockDim.x + threadIdx.x;
    int nth = gridDim.x * blockDim.x;
    for (int i = tid; i < 2 * NB * H; i += nth)
        ((float*)g_hbuf)[i] = 0.0f;
    if (tid < NCTA) g_arrive[tid] = 0u;
}

// ---------------- prep kernels ----------------
__global__ void prepA_kernel(const float* __restrict__ x, __nv_bfloat16* __restrict__ A) {
    long i = (long)blockIdx.x * blockDim.x + threadIdx.x;
    if (i >= (long)BT * D_IN) return;
    int k = (int)(i % D_IN);
    long row = i / D_IN;              // b*512 + t
    int b = (int)(row >> 9), t = (int)(row & 511);
    float v = x[i];
    __nv_bfloat16 hi = __float2bfloat16(v);
    __nv_bfloat16 lo = __float2bfloat16(v - __bfloat162float(hi));
    long orow = ((long)t * 64 + b) * (3 * D_IN);
    A[orow + k] = hi;
    A[orow + D_IN + k] = lo;
    A[orow + 2 * D_IN + k] = hi;
}

__global__ void prepB_kernel(const float* __restrict__ W, int Kin, __nv_bfloat16* __restrict__ Bm) {
    int i = blockIdx.x * blockDim.x + threadIdx.x;
    if (i >= G3 * Kin) return;
    int n = i / Kin, k = i % Kin;
    float v = W[(size_t)k * G3 + n];
    __nv_bfloat16 hi = __float2bfloat16(v);
    __nv_bfloat16 lo = __float2bfloat16(v - __bfloat162float(hi));
    size_t o = (size_t)n * (3 * Kin);
    Bm[o + k] = hi;
    Bm[o + Kin + k] = hi;
    Bm[o + 2 * Kin + k] = lo;
}

// ---------------- HMMA GEMM ----------------
// C[32768 x 768] (+=) A'[32768 x K] @ B'[768 x K]^T (+bias). 128x128 CTA tile.
__global__ void __launch_bounds__(256)
gemm_mma(const __nv_bfloat16* __restrict__ A, const __nv_bfloat16* __restrict__ Bm,
         int K, const float* __restrict__ bias, float* __restrict__ C, int acc)
{
    __shared__ __align__(1024) char smA[2][8192];
    __shared__ __align__(1024) char smB[2][8192];

    const int tid = threadIdx.x;
    const int wid = tid >> 5, lid = tid & 31;
    const int warp_m = wid & 3, warp_n = wid >> 2;
    const int m0 = blockIdx.y * 128, n0 = blockIdx.x * 128;

    const __nv_bfloat16* Ag = A + (size_t)m0 * K;
    const __nv_bfloat16* Bg = Bm + (size_t)n0 * K;

    const uint32_t sA[2] = { smem_u32(smA[0]), smem_u32(smA[1]) };
    const uint32_t sB[2] = { smem_u32(smB[0]), smem_u32(smB[1]) };

    const int lrow0 = tid >> 2;
    const int lc    = tid & 3;
    const uint32_t loff0 = sw_off(lrow0, lc);
    const uint32_t loff1 = sw_off(lrow0 + 64, lc);

    float accf[2][8][4];
#pragma unroll
    for (int i = 0; i < 2; i++)
#pragma unroll
        for (int j = 0; j < 8; j++)
#pragma unroll
            for (int q = 0; q < 4; q++) accf[i][j][q] = 0.0f;

    const int nk = K >> 5;

    {
        const char* ga0 = (const char*)(Ag + (size_t)lrow0 * K + lc * 8);
        const char* ga1 = (const char*)(Ag + (size_t)(lrow0 + 64) * K + lc * 8);
        const char* gb0 = (const char*)(Bg + (size_t)lrow0 * K + lc * 8);
        const char* gb1 = (const char*)(Bg + (size_t)(lrow0 + 64) * K + lc * 8);
        cp16(sA[0] + loff0, ga0); cp16(sA[0] + loff1, ga1);
        cp16(sB[0] + loff0, gb0); cp16(sB[0] + loff1, gb1);
        cp_commit();
    }

    const int a_row = (lid & 15);
    const int a_cd  = (lid >> 4);
    const int b_row = (lid & 7) + ((lid >> 4) & 1) * 8;
    const int b_cd  = (lid >> 3) & 1;

    for (int kc = 0; kc < nk; kc++) {
        if (kc + 1 < nk) {
            int koff = (kc + 1) * 32;
            int st = (kc + 1) & 1;
            const char* ga0 = (const char*)(Ag + (size_t)lrow0 * K + koff + lc * 8);
            const char* ga1 = (const char*)(Ag + (size_t)(lrow0 + 64) * K + koff + lc * 8);
            const char* gb0 = (const char*)(Bg + (size_t)lrow0 * K + koff + lc * 8);
            const char* gb1 = (const char*)(Bg + (size_t)(lrow0 + 64) * K + koff + lc * 8);
            cp16(sA[st] + loff0, ga0); cp16(sA[st] + loff1, ga1);
            cp16(sB[st] + loff0, gb0); cp16(sB[st] + loff1, gb1);
        }
        cp_commit();
        cp_wait1();
        __syncthreads();

        const uint32_t aT = sA[kc & 1], bT = sB[kc & 1];
#pragma unroll
        for (int ks = 0; ks < 2; ks++) {
            uint32_t afr[2][4];
#pragma unroll
            for (int fm = 0; fm < 2; fm++) {
                int row = warp_m * 32 + fm * 16 + a_row;
                ldsm_x4(afr[fm][0], afr[fm][1], afr[fm][2], afr[fm][3],
                        aT + sw_off(row, 2 * ks + a_cd));
            }
            uint32_t bfr[8][2];
#pragma unroll
            for (int ng = 0; ng < 4; ng++) {
                int row = warp_n * 64 + ng * 16 + b_row;
                uint32_t r0, r1, r2, r3;
                ldsm_x4(r0, r1, r2, r3, bT + sw_off(row, 2 * ks + b_cd));
                bfr[ng * 2][0] = r0;     bfr[ng * 2][1] = r1;
                bfr[ng * 2 + 1][0] = r2; bfr[ng * 2 + 1][1] = r3;
            }
#pragma unroll
            for (int fm = 0; fm < 2; fm++)
#pragma unroll
                for (int fn = 0; fn < 8; fn++)
                    mma_bf16(accf[fm][fn], afr[fm], bfr[fn]);
        }
        __syncthreads();
    }

#pragma unroll
    for (int fm = 0; fm < 2; fm++) {
        int row = m0 + warp_m * 32 + fm * 16 + (lid >> 2);
#pragma unroll
        for (int fn = 0; fn < 8; fn++) {
            int colg = n0 + warp_n * 64 + fn * 8 + (lid & 3) * 2;
            float2 v0 = make_float2(accf[fm][fn][0], accf[fm][fn][1]);
            float2 v1 = make_float2(accf[fm][fn][2], accf[fm][fn][3]);
            if (bias) {
                float b0 = bias[colg], b1 = bias[colg + 1];
                v0.x += b0; v0.y += b1; v1.x += b0; v1.y += b1;
            }
            float* p0 = C + (size_t)row * G3 + colg;
            float* p1 = C + (size_t)(row + 8) * G3 + colg;
            if (acc) {
                float2 o0 = *(const float2*)p0;
                float2 o1 = *(const float2*)p1;
                v0.x += o0.x; v0.y += o0.y; v1.x += o1.x; v1.y += o1.y;
            }
            *(float2*)p0 = v0;
            *(float2*)p1 = v1;
        }
    }
}

// ---------------- persistent recurrent scan ----------------
#define SCAN_SMEM ((6*256 + 256*64 + 64*2*3) * 4)

__device__ __forceinline__ float sigmoidf_(float x) {
    return 1.0f / (1.0f + __expf(-x));
}

__global__ void __launch_bounds__(256, 1)
scan_kernel(const float* __restrict__ gi, const float* __restrict__ Whh,
            const float* __restrict__ bhh, const float* __restrict__ tau,
            float* __restrict__ out, int outc0, __nv_bfloat16* __restrict__ a3)
{
    extern __shared__ float smem[];
    float* ws   = smem;                    // 6*256
    float* hs   = ws + 6 * 256;            // 256x64 swizzled: hs[k*64 + (b^((k>>2)&31))]
    float* part = hs + 256 * 64;           // [64][2][3]

    const int cblk = blockIdx.x;
    const int tid = threadIdx.x;
    const int b   = tid & 63;
    const int s   = tid >> 6;
    const int jj  = s & 1;
    const int kh  = s >> 1;
    const int col = 2 * cblk + jj;

    for (int i = tid; i < 6 * 256; i += 256) {
        int gj = i >> 8;
        int k  = i & 255;
        int g  = gj >> 1, j2 = gj & 1;
        ws[gj * 256 + k] = Whh[(size_t)k * G3 + g * H + 2 * cblk + j2];
    }

    const float invt = 1.0f / tau[0];
    const float br = bhh[col], bz = bhh[H + col], bn = bhh[2 * H + col];
    const float* wr = ws + (0 * 2 + jj) * 256 + kh * 128;
    const float* wz = ws + (1 * 2 + jj) * 256 + kh * 128;
    const float* wn = ws + (2 * 2 + jj) * 256 + kh * 128;
    const int kbase = kh * 128;

    for (int t = 0; t < NT; t++) {
        // prefetch gi[t] early (independent of h broadcast)
        float xr = 0.0f, xz = 0.0f, xn = 0.0f;
        if (!kh) {
            const float* gir = gi + ((size_t)t * 64 + b) * G3;
            xr = gir[col]; xz = gir[H + col]; xn = gir[2 * H + col];
        }

        const float* hOldT = g_hbuf[t & 1];          // [col][b]
        float*       hNewT = g_hbuf[(t & 1) ^ 1];

        // broadcast h_old^T into swizzled smem
        {
            const float4* src = (const float4*)hOldT;
#pragma unroll
            for (int n = 0; n < 16; n++) {
                int F = n * 256 + tid;               // 4096 float4 total
                float4 v = src[F];
                int k  = F >> 4;                     // column (k) index
                int b0 = (F & 15) << 2;              // 4 consecutive b
                int cs = (k >> 2) & 31;
                hs[k * 64 + ((b0 + 0) ^ cs)] = v.x;
                hs[k * 64 + ((b0 + 1) ^ cs)] = v.y;
                hs[k * 64 + ((b0 + 2) ^ cs)] = v.z;
                hs[k * 64 + ((b0 + 3) ^ cs)] = v.w;
            }
        }
        __syncthreads();

        float ar = 0.0f, az = 0.0f, an = 0.0f;
#pragma unroll 8
        for (int k4 = 0; k4 < 128; k4 += 4) {
            int bsw = b ^ (k4 >> 2);
            const float* hp = hs + (kbase + k4) * 64 + bsw;
            float h0 = hp[0], h1v = hp[64], h2v = hp[128], h3v = hp[192];
            float4 r4 = *(const float4*)&wr[k4];
            float4 z4 = *(const float4*)&wz[k4];
            float4 n4 = *(const float4*)&wn[k4];
            ar += h0 * r4.x + h1v * r4.y + h2v * r4.z + h3v * r4.w;
            az += h0 * z4.x + h1v * z4.y + h2v * z4.z + h3v * z4.w;
            an += h0 * n4.x + h1v * n4.y + h2v * n4.z + h3v * n4.w;
        }

        if (kh) {
            float* p = part + (b * 2 + jj) * 3;
            p[0] = ar; p[1] = az; p[2] = an;
        }
        __syncthreads();

        if (!kh) {
            const float* p = part + (b * 2 + jj) * 3;
            ar += p[0]; az += p[1]; an += p[2];
            float r = sigmoidf_(xr + ar + br);
            float z = sigmoidf_(xz + az + bz);
            float n = tanhf(xn + r * (an + bn));
            float hold = hs[col * 64 + (b ^ ((col >> 2) & 31))];
            float hc   = (1.0f - z) * n + z * hold;
            float hnew = hold + invt * (hc - hold);
            hNewT[col * 64 + b] = hnew;                         // coalesced
            out[((size_t)b * NT + t) * 512 + outc0 + col] = hnew;
            if (a3) {
                size_t ro = ((size_t)t * 64 + b) * (3 * H);
                __nv_bfloat16 hi = __float2bfloat16(hnew);
                __nv_bfloat16 lo = __float2bfloat16(hnew - __bfloat162float(hi));
                a3[ro + col] = hi;
                a3[ro + H + col] = lo;
                a3[ro + 2 * H + col] = hi;
            }
        }
        __syncthreads();

        // ---- distributed-flag global barrier ----
        unsigned want = (unsigned)(t + 1);
        if (tid == 0) {
            asm volatile("st.release.gpu.global.u32 [%0], %1;"
                         :: "l"(&g_arrive[cblk]), "r"(want) : "memory");
        }
        if (tid < NCTA) {
            const unsigned* fp = &g_arrive[tid];
            unsigned v;
            do {
                asm volatile("ld.acquire.gpu.global.u32 %0, [%1];"
                             : "=r"(v) : "l"(fp) : "memory");
            } while (v < want);
        }
        __syncthreads();
    }
}

// ---------------- launch ----------------
extern "C" void kernel_launch(void* const* d_in, const int* in_sizes, int n_in,
                              void* d_out, int out_size) {
    const float* x    = (const float*)d_in[0];
    const float* tau1 = (const float*)d_in[1];
    const float* tau2 = (const float*)d_in[2];
    const float* Wih1 = (const float*)d_in[3];
    const float* Whh1 = (const float*)d_in[4];
    const float* bih1 = (const float*)d_in[5];
    const float* bhh1 = (const float*)d_in[6];
    const float* Wih2 = (const float*)d_in[7];
    const float* Whh2 = (const float*)d_in[8];
    const float* bih2 = (const float*)d_in[9];
    const float* bhh2 = (const float*)d_in[10];
    float* out = (float*)d_out;

    float *gi1, *gi2;
    __nv_bfloat16 *Ab, *A3, *B1, *B2, *B3;
    cudaGetSymbolAddress((void**)&gi1, g_gi1);
    cudaGetSymbolAddress((void**)&gi2, g_gi2);
    cudaGetSymbolAddress((void**)&Ab,  g_Abuf);
    cudaGetSymbolAddress((void**)&A3,  g_A3);
    cudaGetSymbolAddress((void**)&B1,  g_B1);
    cudaGetSymbolAddress((void**)&B2,  g_B2);
    cudaGetSymbolAddress((void**)&B3,  g_B3);

    cudaFuncSetAttribute(scan_kernel,
                         cudaFuncAttributeMaxDynamicSharedMemorySize, SCAN_SMEM);

    dim3 ggrid(G3 / 128, BT / 128);   // (6, 256)

    init_kernel<<<8, 256>>>();
    prepA_kernel<<<(int)(((long)BT * D_IN + 255) / 256), 256>>>(x, Ab);
    prepB_kernel<<<(G3 * D_IN + 255) / 256, 256>>>(Wih1, D_IN, B1);
    prepB_kernel<<<(G3 * D_IN + 255) / 256, 256>>>(Wih2, D_IN, B2);
    prepB_kernel<<<(G3 * H + 255) / 256, 256>>>(Wih2 + (size_t)D_IN * G3, H, B3);

    // gi1 = x @ W_ih1 + b_ih1 ; gi2 = x @ W_ih2[:768] + b_ih2   (split-bf16 HMMA)
    gemm_mma<<<ggrid, 256>>>(Ab, B1, 3 * D_IN, bih1, gi1, 0);
    gemm_mma<<<ggrid, 256>>>(Ab, B2, 3 * D_IN, bih2, gi2, 0);

    // cell-1 scan: writes out[:, :, 0:256] and split-bf16 h1 triple
    scan_kernel<<<NCTA, 256, SCAN_SMEM>>>(gi1, Whh1, bhh1, tau1, out, 0, A3);

    init_kernel<<<8, 256>>>();
    // gi2 += h1 @ W_ih2[768:1024]
    gemm_mma<<<ggrid, 256>>>(A3, B3, 3 * H, nullptr, gi2, 1);

    // cell-2 scan: writes out[:, :, 256:512]
    scan_kernel<<<NCTA, 256, SCAN_SMEM>>>(gi2, Whh2, bhh2, tau2, out, 256, nullptr);
}

// round 9
// speedup vs baseline: 1.4634x; 1.4634x over previous
#include <cuda_runtime.h>
#include <cuda_bf16.h>
#include <math.h>
#include <stdint.h>

#define D_IN 768
#define H    256
#define NB   64
#define NT   512
#define BT   (NB*NT)    // 32768
#define G3   768        // 3*H
#define NCTA 128        // scan CTAs (single wave)

// ---------------- scratch (static device arrays: allowed) ----------------
__device__ float g_gi1[BT * (size_t)G3];                 // 96 MB, time-major rows (t*64+b)
__device__ float g_gi2[BT * (size_t)G3];                 // 96 MB
__device__ __nv_bfloat16 g_Abuf[BT * (size_t)(3*D_IN)];  // 144 MB [x_hi|x_lo|x_hi] time-major
__device__ __nv_bfloat16 g_A3[BT * (size_t)(3*H)];       // 48 MB  [h_hi|h_lo|h_hi] time-major
__device__ __nv_bfloat16 g_B1[(size_t)G3 * (3*D_IN)];    // W_ih1^T split-stacked
__device__ __nv_bfloat16 g_B2[(size_t)G3 * (3*D_IN)];    // W_ih2[:768]^T split-stacked
__device__ __nv_bfloat16 g_B3[(size_t)G3 * (3*H)];       // W_ih2[768:]^T split-stacked
__device__ float g_hbuf[2][H * NB];                      // TRANSPOSED: [col][b]
__device__ unsigned g_barcnt;
__device__ volatile unsigned g_bargen;

// ---------------- helpers ----------------
__device__ __forceinline__ uint32_t smem_u32(const void* p) {
    uint32_t a;
    asm("{ .reg .u64 t; cvta.to.shared.u64 t, %1; cvt.u32.u64 %0, t; }" : "=r"(a) : "l"(p));
    return a;
}
__device__ __forceinline__ void ldsm_x4(uint32_t& r0, uint32_t& r1, uint32_t& r2, uint32_t& r3,
                                        uint32_t addr) {
    asm volatile("ldmatrix.sync.aligned.m8n8.x4.shared.b16 {%0,%1,%2,%3}, [%4];"
                 : "=r"(r0), "=r"(r1), "=r"(r2), "=r"(r3) : "r"(addr));
}
__device__ __forceinline__ void mma_bf16(float* c, const uint32_t* a, const uint32_t* b) {
    asm volatile("mma.sync.aligned.m16n8k16.row.col.f32.bf16.bf16.f32 "
                 "{%0,%1,%2,%3}, {%4,%5,%6,%7}, {%8,%9}, {%0,%1,%2,%3};"
                 : "+f"(c[0]), "+f"(c[1]), "+f"(c[2]), "+f"(c[3])
                 : "r"(a[0]), "r"(a[1]), "r"(a[2]), "r"(a[3]), "r"(b[0]), "r"(b[1]));
}
__device__ __forceinline__ void cp16(uint32_t dst, const void* src) {
    asm volatile("cp.async.cg.shared.global [%0], [%1], 16;" :: "r"(dst), "l"(src));
}
__device__ __forceinline__ void cp_commit() { asm volatile("cp.async.commit_group;"); }
__device__ __forceinline__ void cp_wait1()  { asm volatile("cp.async.wait_group 1;"); }

// swizzled byte offset inside a 128row x 32col bf16 tile (64B rows, 16B chunks)
__device__ __forceinline__ uint32_t sw_off(int row, int c) {
    return ((uint32_t)row << 6) + (((uint32_t)(c ^ ((row >> 1) & 3))) << 4);
}

// ---------------- init ----------------
__global__ void init_kernel() {
    int tid = blockIdx.x * blockDim.x + threadIdx.x;
    int nth = gridDim.x * blockDim.x;
    for (int i = tid; i < 2 * NB * H; i += nth)
        ((float*)g_hbuf)[i] = 0.0f;
    if (tid == 0) { g_barcnt = 0u; g_bargen = 0u; }
}

// ---------------- prep kernels ----------------
__global__ void prepA_kernel(const float* __restrict__ x, __nv_bfloat16* __restrict__ A) {
    long i = (long)blockIdx.x * blockDim.x + threadIdx.x;
    if (i >= (long)BT * D_IN) return;
    int k = (int)(i % D_IN);
    long row = i / D_IN;              // b*512 + t
    int b = (int)(row >> 9), t = (int)(row & 511);
    float v = x[i];
    __nv_bfloat16 hi = __float2bfloat16(v);
    __nv_bfloat16 lo = __float2bfloat16(v - __bfloat162float(hi));
    long orow = ((long)t * 64 + b) * (3 * D_IN);
    A[orow + k] = hi;
    A[orow + D_IN + k] = lo;
    A[orow + 2 * D_IN + k] = hi;
}

__device__ __forceinline__ void prep_one(const float* __restrict__ W, int Kin,
                                         __nv_bfloat16* __restrict__ Bm, long idx) {
    int n = (int)(idx / Kin), k = (int)(idx % Kin);
    float v = W[(size_t)k * G3 + n];
    __nv_bfloat16 hi = __float2bfloat16(v);
    __nv_bfloat16 lo = __float2bfloat16(v - __bfloat162float(hi));
    size_t o = (size_t)n * (3 * Kin);
    Bm[o + k] = hi;
    Bm[o + Kin + k] = hi;
    Bm[o + 2 * Kin + k] = lo;
}

// all three weight transposes in ONE launch
__global__ void prepB_all(const float* __restrict__ W1, const float* __restrict__ W2,
                          const float* __restrict__ W3,
                          __nv_bfloat16* __restrict__ B1, __nv_bfloat16* __restrict__ B2,
                          __nv_bfloat16* __restrict__ B3) {
    long i = (long)blockIdx.x * blockDim.x + threadIdx.x;
    const long n1 = (long)G3 * D_IN;
    const long n3 = (long)G3 * H;
    if (i < n1)               prep_one(W1, D_IN, B1, i);
    else if (i < 2 * n1)      prep_one(W2, D_IN, B2, i - n1);
    else if (i < 2 * n1 + n3) prep_one(W3, H,    B3, i - 2 * n1);
}

// ---------------- HMMA GEMM ----------------
// C[32768 x 768] (+=) A'[32768 x K] @ B'[768 x K]^T (+bias). 128x128 CTA tile.
__global__ void __launch_bounds__(256)
gemm_mma(const __nv_bfloat16* __restrict__ A, const __nv_bfloat16* __restrict__ Bm,
         int K, const float* __restrict__ bias, float* __restrict__ C, int acc)
{
    __shared__ __align__(1024) char smA[2][8192];
    __shared__ __align__(1024) char smB[2][8192];

    const int tid = threadIdx.x;
    const int wid = tid >> 5, lid = tid & 31;
    const int warp_m = wid & 3, warp_n = wid >> 2;
    const int m0 = blockIdx.y * 128, n0 = blockIdx.x * 128;

    const __nv_bfloat16* Ag = A + (size_t)m0 * K;
    const __nv_bfloat16* Bg = Bm + (size_t)n0 * K;

    const uint32_t sA[2] = { smem_u32(smA[0]), smem_u32(smA[1]) };
    const uint32_t sB[2] = { smem_u32(smB[0]), smem_u32(smB[1]) };

    const int lrow0 = tid >> 2;
    const int lc    = tid & 3;
    const uint32_t loff0 = sw_off(lrow0, lc);
    const uint32_t loff1 = sw_off(lrow0 + 64, lc);

    float accf[2][8][4];
#pragma unroll
    for (int i = 0; i < 2; i++)
#pragma unroll
        for (int j = 0; j < 8; j++)
#pragma unroll
            for (int q = 0; q < 4; q++) accf[i][j][q] = 0.0f;

    const int nk = K >> 5;

    {
        const char* ga0 = (const char*)(Ag + (size_t)lrow0 * K + lc * 8);
        const char* ga1 = (const char*)(Ag + (size_t)(lrow0 + 64) * K + lc * 8);
        const char* gb0 = (const char*)(Bg + (size_t)lrow0 * K + lc * 8);
        const char* gb1 = (const char*)(Bg + (size_t)(lrow0 + 64) * K + lc * 8);
        cp16(sA[0] + loff0, ga0); cp16(sA[0] + loff1, ga1);
        cp16(sB[0] + loff0, gb0); cp16(sB[0] + loff1, gb1);
        cp_commit();
    }

    const int a_row = (lid & 15);
    const int a_cd  = (lid >> 4);
    const int b_row = (lid & 7) + ((lid >> 4) & 1) * 8;
    const int b_cd  = (lid >> 3) & 1;

    for (int kc = 0; kc < nk; kc++) {
        if (kc + 1 < nk) {
            int koff = (kc + 1) * 32;
            int st = (kc + 1) & 1;
            const char* ga0 = (const char*)(Ag + (size_t)lrow0 * K + koff + lc * 8);
            const char* ga1 = (const char*)(Ag + (size_t)(lrow0 + 64) * K + koff + lc * 8);
            const char* gb0 = (const char*)(Bg + (size_t)lrow0 * K + koff + lc * 8);
            const char* gb1 = (const char*)(Bg + (size_t)(lrow0 + 64) * K + koff + lc * 8);
            cp16(sA[st] + loff0, ga0); cp16(sA[st] + loff1, ga1);
            cp16(sB[st] + loff0, gb0); cp16(sB[st] + loff1, gb1);
        }
        cp_commit();
        cp_wait1();
        __syncthreads();

        const uint32_t aT = sA[kc & 1], bT = sB[kc & 1];
#pragma unroll
        for (int ks = 0; ks < 2; ks++) {
            uint32_t afr[2][4];
#pragma unroll
            for (int fm = 0; fm < 2; fm++) {
                int row = warp_m * 32 + fm * 16 + a_row;
                ldsm_x4(afr[fm][0], afr[fm][1], afr[fm][2], afr[fm][3],
                        aT + sw_off(row, 2 * ks + a_cd));
            }
            uint32_t bfr[8][2];
#pragma unroll
            for (int ng = 0; ng < 4; ng++) {
                int row = warp_n * 64 + ng * 16 + b_row;
                uint32_t r0, r1, r2, r3;
                ldsm_x4(r0, r1, r2, r3, bT + sw_off(row, 2 * ks + b_cd));
                bfr[ng * 2][0] = r0;     bfr[ng * 2][1] = r1;
                bfr[ng * 2 + 1][0] = r2; bfr[ng * 2 + 1][1] = r3;
            }
#pragma unroll
            for (int fm = 0; fm < 2; fm++)
#pragma unroll
                for (int fn = 0; fn < 8; fn++)
                    mma_bf16(accf[fm][fn], afr[fm], bfr[fn]);
        }
        __syncthreads();
    }

#pragma unroll
    for (int fm = 0; fm < 2; fm++) {
        int row = m0 + warp_m * 32 + fm * 16 + (lid >> 2);
#pragma unroll
        for (int fn = 0; fn < 8; fn++) {
            int colg = n0 + warp_n * 64 + fn * 8 + (lid & 3) * 2;
            float2 v0 = make_float2(accf[fm][fn][0], accf[fm][fn][1]);
            float2 v1 = make_float2(accf[fm][fn][2], accf[fm][fn][3]);
            if (bias) {
                float b0 = bias[colg], b1 = bias[colg + 1];
                v0.x += b0; v0.y += b1; v1.x += b0; v1.y += b1;
            }
            float* p0 = C + (size_t)row * G3 + colg;
            float* p1 = C + (size_t)(row + 8) * G3 + colg;
            if (acc) {
                float2 o0 = *(const float2*)p0;
                float2 o1 = *(const float2*)p1;
                v0.x += o0.x; v0.y += o0.y; v1.x += o1.x; v1.y += o1.y;
            }
            *(float2*)p0 = v0;
            *(float2*)p1 = v1;
        }
    }
}

// ---------------- persistent recurrent scan ----------------
#define SCAN_SMEM ((6*256 + 256*64 + 64*2*3) * 4)

__device__ __forceinline__ float sigmoidf_(float x) {
    return 1.0f / (1.0f + __expf(-x));
}

__global__ void __launch_bounds__(256, 1)
scan_kernel(const float* __restrict__ gi, const float* __restrict__ Whh,
            const float* __restrict__ bhh, const float* __restrict__ tau,
            float* __restrict__ out, int outc0, __nv_bfloat16* __restrict__ a3)
{
    extern __shared__ float smem[];
    float* ws   = smem;                    // 6*256
    float* hs   = ws + 6 * 256;            // 256x64 swizzled: hs[k*64 + (b^((k>>2)&31))]
    float* part = hs + 256 * 64;           // [64][2][3]

    const int cblk = blockIdx.x;
    const int tid = threadIdx.x;
    const int b   = tid & 63;
    const int s   = tid >> 6;
    const int jj  = s & 1;
    const int kh  = s >> 1;
    const int col = 2 * cblk + jj;

    for (int i = tid; i < 6 * 256; i += 256) {
        int gj = i >> 8;
        int k  = i & 255;
        int g  = gj >> 1, j2 = gj & 1;
        ws[gj * 256 + k] = Whh[(size_t)k * G3 + g * H + 2 * cblk + j2];
    }

    const float invt = 1.0f / tau[0];
    const float br = bhh[col], bz = bhh[H + col], bn = bhh[2 * H + col];
    const float* wr = ws + (0 * 2 + jj) * 256 + kh * 128;
    const float* wz = ws + (1 * 2 + jj) * 256 + kh * 128;
    const float* wn = ws + (2 * 2 + jj) * 256 + kh * 128;
    const int kbase = kh * 128;

    for (int t = 0; t < NT; t++) {
        // prefetch gi[t] early (independent of h broadcast)
        float xr = 0.0f, xz = 0.0f, xn = 0.0f;
        if (!kh) {
            const float* gir = gi + ((size_t)t * 64 + b) * G3;
            xr = gir[col]; xz = gir[H + col]; xn = gir[2 * H + col];
        }

        const float* hOldT = g_hbuf[t & 1];          // [col][b]
        float*       hNewT = g_hbuf[(t & 1) ^ 1];

        // broadcast h_old^T into swizzled smem (coalesced float4 loads)
        {
            const float4* src = (const float4*)hOldT;
#pragma unroll
            for (int n = 0; n < 16; n++) {
                int F = n * 256 + tid;               // 4096 float4 total
                float4 v = src[F];
                int k  = F >> 4;                     // column (k) index
                int b0 = (F & 15) << 2;              // 4 consecutive b
                int cs = (k >> 2) & 31;
                hs[k * 64 + ((b0 + 0) ^ cs)] = v.x;
                hs[k * 64 + ((b0 + 1) ^ cs)] = v.y;
                hs[k * 64 + ((b0 + 2) ^ cs)] = v.z;
                hs[k * 64 + ((b0 + 3) ^ cs)] = v.w;
            }
        }
        __syncthreads();

        float ar = 0.0f, az = 0.0f, an = 0.0f;
#pragma unroll 8
        for (int k4 = 0; k4 < 128; k4 += 4) {
            int bsw = b ^ (k4 >> 2);
            const float* hp = hs + (kbase + k4) * 64 + bsw;
            float h0 = hp[0], h1v = hp[64], h2v = hp[128], h3v = hp[192];
            float4 r4 = *(const float4*)&wr[k4];
            float4 z4 = *(const float4*)&wz[k4];
            float4 n4 = *(const float4*)&wn[k4];
            ar += h0 * r4.x + h1v * r4.y + h2v * r4.z + h3v * r4.w;
            az += h0 * z4.x + h1v * z4.y + h2v * z4.z + h3v * z4.w;
            an += h0 * n4.x + h1v * n4.y + h2v * n4.z + h3v * n4.w;
        }

        if (kh) {
            float* p = part + (b * 2 + jj) * 3;
            p[0] = ar; p[1] = az; p[2] = an;
        }
        __syncthreads();

        if (!kh) {
            const float* p = part + (b * 2 + jj) * 3;
            ar += p[0]; az += p[1]; an += p[2];
            float r = sigmoidf_(xr + ar + br);
            float z = sigmoidf_(xz + az + bz);
            float n = tanhf(xn + r * (an + bn));
            float hold = hs[col * 64 + (b ^ ((col >> 2) & 31))];
            float hc   = (1.0f - z) * n + z * hold;
            float hnew = hold + invt * (hc - hold);
            hNewT[col * 64 + b] = hnew;                         // coalesced
            out[((size_t)b * NT + t) * 512 + outc0 + col] = hnew;
            if (a3) {
                size_t ro = ((size_t)t * 64 + b) * (3 * H);
                __nv_bfloat16 hi = __float2bfloat16(hnew);
                __nv_bfloat16 lo = __float2bfloat16(hnew - __bfloat162float(hi));
                a3[ro + col] = hi;
                a3[ro + H + col] = lo;
                a3[ro + 2 * H + col] = hi;
            }
            __threadfence();   // make this thread's h/out/a3 writes visible pre-barrier
        }
        __syncthreads();

        // ---- proven gen-counter global barrier (R4/R7) ----
        if (tid == 0) {
            __threadfence();
            unsigned arrived = atomicAdd(&g_barcnt, 1u);
            unsigned want = (unsigned)(t + 1);
            if (arrived == NCTA - 1) {
                g_barcnt = 0u;
                __threadfence();
                g_bargen = want;
            } else {
                while (g_bargen < want) { }
                __threadfence();
            }
        }
        __syncthreads();
    }
}

// ---------------- launch ----------------
extern "C" void kernel_launch(void* const* d_in, const int* in_sizes, int n_in,
                              void* d_out, int out_size) {
    const float* x    = (const float*)d_in[0];
    const float* tau1 = (const float*)d_in[1];
    const float* tau2 = (const float*)d_in[2];
    const float* Wih1 = (const float*)d_in[3];
    const float* Whh1 = (const float*)d_in[4];
    const float* bih1 = (const float*)d_in[5];
    const float* bhh1 = (const float*)d_in[6];
    const float* Wih2 = (const float*)d_in[7];
    const float* Whh2 = (const float*)d_in[8];
    const float* bih2 = (const float*)d_in[9];
    const float* bhh2 = (const float*)d_in[10];
    float* out = (float*)d_out;

    float *gi1, *gi2;
    __nv_bfloat16 *Ab, *A3, *B1, *B2, *B3;
    cudaGetSymbolAddress((void**)&gi1, g_gi1);
    cudaGetSymbolAddress((void**)&gi2, g_gi2);
    cudaGetSymbolAddress((void**)&Ab,  g_Abuf);
    cudaGetSymbolAddress((void**)&A3,  g_A3);
    cudaGetSymbolAddress((void**)&B1,  g_B1);
    cudaGetSymbolAddress((void**)&B2,  g_B2);
    cudaGetSymbolAddress((void**)&B3,  g_B3);

    cudaFuncSetAttribute(scan_kernel,
                         cudaFuncAttributeMaxDynamicSharedMemorySize, SCAN_SMEM);

    dim3 ggrid(G3 / 128, BT / 128);   // (6, 256)

    // launch order arranged so the ncu capture window (-s 5 -c 1) lands on
    // gemm2/scan1 instead of prep kernels.
    init_kernel<<<8, 256>>>();                                              // 0
    prepA_kernel<<<(int)(((long)BT * D_IN + 255) / 256), 256>>>(x, Ab);     // 1
    {
        long tot = 2L * G3 * D_IN + (long)G3 * H;
        prepB_all<<<(int)((tot + 255) / 256), 256>>>(
            Wih1, Wih2, Wih2 + (size_t)D_IN * G3, B1, B2, B3);              // 2
    }
    gemm_mma<<<ggrid, 256>>>(Ab, B1, 3 * D_IN, bih1, gi1, 0);               // 3
    gemm_mma<<<ggrid, 256>>>(Ab, B2, 3 * D_IN, bih2, gi2, 0);               // 4
    scan_kernel<<<NCTA, 256, SCAN_SMEM>>>(gi1, Whh1, bhh1, tau1, out, 0, A3); // 5
    init_kernel<<<8, 256>>>();                                              // 6
    gemm_mma<<<ggrid, 256>>>(A3, B3, 3 * H, nullptr, gi2, 1);               // 7
    scan_kernel<<<NCTA, 256, SCAN_SMEM>>>(gi2, Whh2, bhh2, tau2, out, 256, nullptr); // 8
}

// round 10
// speedup vs baseline: 1.7560x; 1.1999x over previous
#include <cuda_runtime.h>
#include <cuda_bf16.h>
#include <math.h>
#include <stdint.h>

#define D_IN 768
#define H    256
#define NB   64
#define NT   512
#define BT   (NB*NT)    // 32768
#define G3   768        // 3*H
#define NCTA 128        // scan CTAs (single wave)

// ---------------- scratch (static device arrays: allowed) ----------------
__device__ float g_gi1[BT * (size_t)G3];                 // 96 MB, time-major rows (t*64+b)
__device__ float g_gi2[BT * (size_t)G3];                 // 96 MB
__device__ __nv_bfloat16 g_Abuf[BT * (size_t)(3*D_IN)];  // 144 MB [x_hi|x_lo|x_hi] time-major
__device__ __nv_bfloat16 g_A3[BT * (size_t)(3*H)];       // 48 MB  [h_hi|h_lo|h_hi] time-major
__device__ __nv_bfloat16 g_B1[(size_t)G3 * (3*D_IN)];    // W_ih1^T split-stacked
__device__ __nv_bfloat16 g_B2[(size_t)G3 * (3*D_IN)];    // W_ih2[:768]^T split-stacked
__device__ __nv_bfloat16 g_B3[(size_t)G3 * (3*H)];       // W_ih2[768:]^T split-stacked
__device__ float g_hbuf[2][NB * H];                      // [b][k] fp32
__device__ unsigned g_barcnt;
__device__ volatile unsigned g_bargen;

// ---------------- helpers ----------------
__device__ __forceinline__ uint32_t smem_u32(const void* p) {
    uint32_t a;
    asm("{ .reg .u64 t; cvta.to.shared.u64 t, %1; cvt.u32.u64 %0, t; }" : "=r"(a) : "l"(p));
    return a;
}
__device__ __forceinline__ void ldsm_x4(uint32_t& r0, uint32_t& r1, uint32_t& r2, uint32_t& r3,
                                        uint32_t addr) {
    asm volatile("ldmatrix.sync.aligned.m8n8.x4.shared.b16 {%0,%1,%2,%3}, [%4];"
                 : "=r"(r0), "=r"(r1), "=r"(r2), "=r"(r3) : "r"(addr));
}
__device__ __forceinline__ void mma_bf16(float* c, const uint32_t* a, const uint32_t* b) {
    asm volatile("mma.sync.aligned.m16n8k16.row.col.f32.bf16.bf16.f32 "
                 "{%0,%1,%2,%3}, {%4,%5,%6,%7}, {%8,%9}, {%0,%1,%2,%3};"
                 : "+f"(c[0]), "+f"(c[1]), "+f"(c[2]), "+f"(c[3])
                 : "r"(a[0]), "r"(a[1]), "r"(a[2]), "r"(a[3]), "r"(b[0]), "r"(b[1]));
}
__device__ __forceinline__ void cp16(uint32_t dst, const void* src) {
    asm volatile("cp.async.cg.shared.global [%0], [%1], 16;" :: "r"(dst), "l"(src));
}
__device__ __forceinline__ void cp_commit() { asm volatile("cp.async.commit_group;"); }
__device__ __forceinline__ void cp_wait1()  { asm volatile("cp.async.wait_group 1;"); }

// swizzled byte offset inside a 128row x 32col bf16 tile (64B rows, 16B chunks)
__device__ __forceinline__ uint32_t sw_off(int row, int c) {
    return ((uint32_t)row << 6) + (((uint32_t)(c ^ ((row >> 1) & 3))) << 4);
}

// ---------------- init ----------------
__global__ void init_kernel() {
    int tid = blockIdx.x * blockDim.x + threadIdx.x;
    int nth = gridDim.x * blockDim.x;
    for (int i = tid; i < 2 * NB * H; i += nth)
        ((float*)g_hbuf)[i] = 0.0f;
    if (tid == 0) { g_barcnt = 0u; g_bargen = 0u; }
}

// ---------------- prep kernels ----------------
__global__ void prepA_kernel(const float* __restrict__ x, __nv_bfloat16* __restrict__ A) {
    long i = (long)blockIdx.x * blockDim.x + threadIdx.x;
    if (i >= (long)BT * D_IN) return;
    int k = (int)(i % D_IN);
    long row = i / D_IN;              // b*512 + t
    int b = (int)(row >> 9), t = (int)(row & 511);
    float v = x[i];
    __nv_bfloat16 hi = __float2bfloat16(v);
    __nv_bfloat16 lo = __float2bfloat16(v - __bfloat162float(hi));
    long orow = ((long)t * 64 + b) * (3 * D_IN);
    A[orow + k] = hi;
    A[orow + D_IN + k] = lo;
    A[orow + 2 * D_IN + k] = hi;
}

__device__ __forceinline__ void prep_one(const float* __restrict__ W, int Kin,
                                         __nv_bfloat16* __restrict__ Bm, long idx) {
    int n = (int)(idx / Kin), k = (int)(idx % Kin);
    float v = W[(size_t)k * G3 + n];
    __nv_bfloat16 hi = __float2bfloat16(v);
    __nv_bfloat16 lo = __float2bfloat16(v - __bfloat162float(hi));
    size_t o = (size_t)n * (3 * Kin);
    Bm[o + k] = hi;
    Bm[o + Kin + k] = hi;
    Bm[o + 2 * Kin + k] = lo;
}

__global__ void prepB_all(const float* __restrict__ W1, const float* __restrict__ W2,
                          const float* __restrict__ W3,
                          __nv_bfloat16* __restrict__ B1, __nv_bfloat16* __restrict__ B2,
                          __nv_bfloat16* __restrict__ B3) {
    long i = (long)blockIdx.x * blockDim.x + threadIdx.x;
    const long n1 = (long)G3 * D_IN;
    const long n3 = (long)G3 * H;
    if (i < n1)               prep_one(W1, D_IN, B1, i);
    else if (i < 2 * n1)      prep_one(W2, D_IN, B2, i - n1);
    else if (i < 2 * n1 + n3) prep_one(W3, H,    B3, i - 2 * n1);
}

// ---------------- HMMA GEMM (unchanged, proven) ----------------
__global__ void __launch_bounds__(256)
gemm_mma(const __nv_bfloat16* __restrict__ A, const __nv_bfloat16* __restrict__ Bm,
         int K, const float* __restrict__ bias, float* __restrict__ C, int acc)
{
    __shared__ __align__(1024) char smA[2][8192];
    __shared__ __align__(1024) char smB[2][8192];

    const int tid = threadIdx.x;
    const int wid = tid >> 5, lid = tid & 31;
    const int warp_m = wid & 3, warp_n = wid >> 2;
    const int m0 = blockIdx.y * 128, n0 = blockIdx.x * 128;

    const __nv_bfloat16* Ag = A + (size_t)m0 * K;
    const __nv_bfloat16* Bg = Bm + (size_t)n0 * K;

    const uint32_t sA[2] = { smem_u32(smA[0]), smem_u32(smA[1]) };
    const uint32_t sB[2] = { smem_u32(smB[0]), smem_u32(smB[1]) };

    const int lrow0 = tid >> 2;
    const int lc    = tid & 3;
    const uint32_t loff0 = sw_off(lrow0, lc);
    const uint32_t loff1 = sw_off(lrow0 + 64, lc);

    float accf[2][8][4];
#pragma unroll
    for (int i = 0; i < 2; i++)
#pragma unroll
        for (int j = 0; j < 8; j++)
#pragma unroll
            for (int q = 0; q < 4; q++) accf[i][j][q] = 0.0f;

    const int nk = K >> 5;

    {
        const char* ga0 = (const char*)(Ag + (size_t)lrow0 * K + lc * 8);
        const char* ga1 = (const char*)(Ag + (size_t)(lrow0 + 64) * K + lc * 8);
        const char* gb0 = (const char*)(Bg + (size_t)lrow0 * K + lc * 8);
        const char* gb1 = (const char*)(Bg + (size_t)(lrow0 + 64) * K + lc * 8);
        cp16(sA[0] + loff0, ga0); cp16(sA[0] + loff1, ga1);
        cp16(sB[0] + loff0, gb0); cp16(sB[0] + loff1, gb1);
        cp_commit();
    }

    const int a_row = (lid & 15);
    const int a_cd  = (lid >> 4);
    const int b_row = (lid & 7) + ((lid >> 4) & 1) * 8;
    const int b_cd  = (lid >> 3) & 1;

    for (int kc = 0; kc < nk; kc++) {
        if (kc + 1 < nk) {
            int koff = (kc + 1) * 32;
            int st = (kc + 1) & 1;
            const char* ga0 = (const char*)(Ag + (size_t)lrow0 * K + koff + lc * 8);
            const char* ga1 = (const char*)(Ag + (size_t)(lrow0 + 64) * K + koff + lc * 8);
            const char* gb0 = (const char*)(Bg + (size_t)lrow0 * K + koff + lc * 8);
            const char* gb1 = (const char*)(Bg + (size_t)(lrow0 + 64) * K + koff + lc * 8);
            cp16(sA[st] + loff0, ga0); cp16(sA[st] + loff1, ga1);
            cp16(sB[st] + loff0, gb0); cp16(sB[st] + loff1, gb1);
        }
        cp_commit();
        cp_wait1();
        __syncthreads();

        const uint32_t aT = sA[kc & 1], bT = sB[kc & 1];
#pragma unroll
        for (int ks = 0; ks < 2; ks++) {
            uint32_t afr[2][4];
#pragma unroll
            for (int fm = 0; fm < 2; fm++) {
                int row = warp_m * 32 + fm * 16 + a_row;
                ldsm_x4(afr[fm][0], afr[fm][1], afr[fm][2], afr[fm][3],
                        aT + sw_off(row, 2 * ks + a_cd));
            }
            uint32_t bfr[8][2];
#pragma unroll
            for (int ng = 0; ng < 4; ng++) {
                int row = warp_n * 64 + ng * 16 + b_row;
                uint32_t r0, r1, r2, r3;
                ldsm_x4(r0, r1, r2, r3, bT + sw_off(row, 2 * ks + b_cd));
                bfr[ng * 2][0] = r0;     bfr[ng * 2][1] = r1;
                bfr[ng * 2 + 1][0] = r2; bfr[ng * 2 + 1][1] = r3;
            }
#pragma unroll
            for (int fm = 0; fm < 2; fm++)
#pragma unroll
                for (int fn = 0; fn < 8; fn++)
                    mma_bf16(accf[fm][fn], afr[fm], bfr[fn]);
        }
        __syncthreads();
    }

#pragma unroll
    for (int fm = 0; fm < 2; fm++) {
        int row = m0 + warp_m * 32 + fm * 16 + (lid >> 2);
#pragma unroll
        for (int fn = 0; fn < 8; fn++) {
            int colg = n0 + warp_n * 64 + fn * 8 + (lid & 3) * 2;
            float2 v0 = make_float2(accf[fm][fn][0], accf[fm][fn][1]);
            float2 v1 = make_float2(accf[fm][fn][2], accf[fm][fn][3]);
            if (bias) {
                float b0 = bias[colg], b1 = bias[colg + 1];
                v0.x += b0; v0.y += b1; v1.x += b0; v1.y += b1;
            }
            float* p0 = C + (size_t)row * G3 + colg;
            float* p1 = C + (size_t)(row + 8) * G3 + colg;
            if (acc) {
                float2 o0 = *(const float2*)p0;
                float2 o1 = *(const float2*)p1;
                v0.x += o0.x; v0.y += o0.y; v1.x += o1.x; v1.y += o1.y;
            }
            *(float2*)p0 = v0;
            *(float2*)p1 = v1;
        }
    }
}

// ---------------- persistent recurrent scan (512 threads, f32x2) ----------------
// thread: b = tid&63, kq = tid>>6 (K eighth, 32 k each). Each thread computes
// partial dots for BOTH CTA columns x 3 gates (6 col-gates).
#define SCAN_SMEM ((6*256 + 64*256 + 8*64*6) * 4)   // ws 6KB + hs 64KB + part 12KB

__device__ __forceinline__ float sigmoidf_(float x) {
    return 1.0f / (1.0f + __expf(-x));
}

__global__ void __launch_bounds__(512, 1)
scan_kernel(const float* __restrict__ gi, const float* __restrict__ Whh,
            const float* __restrict__ bhh, const float* __restrict__ tau,
            float* __restrict__ out, int outc0, __nv_bfloat16* __restrict__ a3)
{
    extern __shared__ float smem[];
    float* ws   = smem;                    // [6][256]  (cg = g*2+jj)
    float* hs   = ws + 6 * 256;            // [64][64 float4] swizzled: f4idx = b*64 + (q^(b&15))
    float* part = hs + 64 * 256;           // [8][64][6]

    const int cblk = blockIdx.x;
    const int tid  = threadIdx.x;
    const int b    = tid & 63;
    const int kq   = tid >> 6;             // 0..7
    const int col0 = 2 * cblk;
    const int sb   = b & 15;

    // ws[cg*256 + k] = Whh[k][g*H + col0 + jj],  cg = g*2+jj
    for (int i = tid; i < 6 * 256; i += 512) {
        int cg = i >> 8;
        int k  = i & 255;
        ws[cg * 256 + k] = Whh[(size_t)k * G3 + (cg >> 1) * H + col0 + (cg & 1)];
    }

    const float invt = 1.0f / tau[0];
    float bh[6];
#pragma unroll
    for (int cg = 0; cg < 6; cg++)
        bh[cg] = bhh[(cg >> 1) * H + col0 + (cg & 1)];

    const uint32_t hs_u = smem_u32(hs);
    const uint32_t ws_u = smem_u32(ws);
    const uint32_t hthr = hs_u + ((uint32_t)b << 10);   // b*64 float4 = b<<10 bytes

    for (int t = 0; t < NT; t++) {
        // gi prefetch (kq==0 threads; both cols x 3 gates)
        float x[6];
        if (kq == 0) {
            const float* gir = gi + ((size_t)t * 64 + b) * G3 + col0;
            float2 v0 = *(const float2*)(gir);
            float2 v1 = *(const float2*)(gir + H);
            float2 v2 = *(const float2*)(gir + 2 * H);
            x[0] = v0.x; x[1] = v0.y;
            x[2] = v1.x; x[3] = v1.y;
            x[4] = v2.x; x[5] = v2.y;
        }

        const float* hOld = g_hbuf[t & 1];          // [b][k]
        float*       hNew = g_hbuf[(t & 1) ^ 1];

        // broadcast h into swizzled smem: 4096 float4 / 512 thr = 8 iters, MLP 8
        {
            const float4* src = (const float4*)hOld;
#pragma unroll
            for (int n = 0; n < 8; n++) {
                int F = n * 512 + tid;
                float4 v = src[F];
                int bb = F >> 6;
                int q  = F & 63;
                ((float4*)hs)[bb * 64 + (q ^ (bb & 15))] = v;
            }
        }
        __syncthreads();

        // 6 packed-f32x2 dots over this thread's 32 k
        unsigned long long acc[6] = {0ull, 0ull, 0ull, 0ull, 0ull, 0ull};
#pragma unroll
        for (int i = 0; i < 8; i++) {
            int q = kq * 8 + i;
            unsigned long long h01, h23;
            asm("ld.shared.v2.u64 {%0,%1}, [%2];"
                : "=l"(h01), "=l"(h23) : "r"(hthr + (((uint32_t)(q ^ sb)) << 4)));
#pragma unroll
            for (int cg = 0; cg < 6; cg++) {
                unsigned long long w01, w23;
                asm("ld.shared.v2.u64 {%0,%1}, [%2];"
                    : "=l"(w01), "=l"(w23)
                    : "r"(ws_u + ((uint32_t)cg << 10) + ((uint32_t)q << 4)));
                asm("fma.rn.f32x2 %0, %1, %2, %0;" : "+l"(acc[cg]) : "l"(h01), "l"(w01));
                asm("fma.rn.f32x2 %0, %1, %2, %0;" : "+l"(acc[cg]) : "l"(h23), "l"(w23));
            }
        }

        // partial store
        {
            float* pp = part + (kq * 64 + b) * 6;
#pragma unroll
            for (int cg = 0; cg < 6; cg++) {
                float lo, hi;
                asm("mov.b64 {%0,%1}, %2;" : "=f"(lo), "=f"(hi) : "l"(acc[cg]));
                pp[cg] = lo + hi;
            }
        }
        __syncthreads();

        if (kq == 0) {
            float s[6];
#pragma unroll
            for (int cg = 0; cg < 6; cg++) s[cg] = 0.0f;
#pragma unroll
            for (int k8 = 0; k8 < 8; k8++) {
                const float* pp = part + (k8 * 64 + b) * 6;
#pragma unroll
                for (int cg = 0; cg < 6; cg++) s[cg] += pp[cg];
            }
#pragma unroll
            for (int jj = 0; jj < 2; jj++) {
                int col = col0 + jj;
                float r = sigmoidf_(x[jj]     + s[jj]     + bh[jj]);
                float z = sigmoidf_(x[2 + jj] + s[2 + jj] + bh[2 + jj]);
                float n = tanhf(x[4 + jj] + r * (s[4 + jj] + bh[4 + jj]));
                float hold = hs[(b * 64 + ((col >> 2) ^ sb)) * 4 + (col & 3)];
                float hc   = (1.0f - z) * n + z * hold;
                float hnew = hold + invt * (hc - hold);
                hNew[b * H + col] = hnew;
                out[((size_t)b * NT + t) * 512 + outc0 + col] = hnew;
                if (a3) {
                    size_t ro = ((size_t)t * 64 + b) * (3 * H);
                    __nv_bfloat16 hi = __float2bfloat16(hnew);
                    __nv_bfloat16 lo = __float2bfloat16(hnew - __bfloat162float(hi));
                    a3[ro + col] = hi;
                    a3[ro + H + col] = lo;
                    a3[ro + 2 * H + col] = hi;
                }
            }
            __threadfence();
        }
        __syncthreads();

        // ---- proven gen-counter global barrier ----
        if (tid == 0) {
            __threadfence();
            unsigned arrived = atomicAdd(&g_barcnt, 1u);
            unsigned want = (unsigned)(t + 1);
            if (arrived == NCTA - 1) {
                g_barcnt = 0u;
                __threadfence();
                g_bargen = want;
            } else {
                while (g_bargen < want) { }
                __threadfence();
            }
        }
        __syncthreads();
    }
}

// ---------------- launch ----------------
extern "C" void kernel_launch(void* const* d_in, const int* in_sizes, int n_in,
                              void* d_out, int out_size) {
    const float* x    = (const float*)d_in[0];
    const float* tau1 = (const float*)d_in[1];
    const float* tau2 = (const float*)d_in[2];
    const float* Wih1 = (const float*)d_in[3];
    const float* Whh1 = (const float*)d_in[4];
    const float* bih1 = (const float*)d_in[5];
    const float* bhh1 = (const float*)d_in[6];
    const float* Wih2 = (const float*)d_in[7];
    const float* Whh2 = (const float*)d_in[8];
    const float* bih2 = (const float*)d_in[9];
    const float* bhh2 = (const float*)d_in[10];
    float* out = (float*)d_out;

    float *gi1, *gi2;
    __nv_bfloat16 *Ab, *A3, *B1, *B2, *B3;
    cudaGetSymbolAddress((void**)&gi1, g_gi1);
    cudaGetSymbolAddress((void**)&gi2, g_gi2);
    cudaGetSymbolAddress((void**)&Ab,  g_Abuf);
    cudaGetSymbolAddress((void**)&A3,  g_A3);
    cudaGetSymbolAddress((void**)&B1,  g_B1);
    cudaGetSymbolAddress((void**)&B2,  g_B2);
    cudaGetSymbolAddress((void**)&B3,  g_B3);

    cudaFuncSetAttribute(scan_kernel,
                         cudaFuncAttributeMaxDynamicSharedMemorySize, SCAN_SMEM);

    dim3 ggrid(G3 / 128, BT / 128);   // (6, 256)

    init_kernel<<<8, 256>>>();                                              // 0
    prepA_kernel<<<(int)(((long)BT * D_IN + 255) / 256), 256>>>(x, Ab);     // 1
    {
        long tot = 2L * G3 * D_IN + (long)G3 * H;
        prepB_all<<<(int)((tot + 255) / 256), 256>>>(
            Wih1, Wih2, Wih2 + (size_t)D_IN * G3, B1, B2, B3);              // 2
    }
    gemm_mma<<<ggrid, 256>>>(Ab, B1, 3 * D_IN, bih1, gi1, 0);               // 3
    gemm_mma<<<ggrid, 256>>>(Ab, B2, 3 * D_IN, bih2, gi2, 0);               // 4
    scan_kernel<<<NCTA, 512, SCAN_SMEM>>>(gi1, Whh1, bhh1, tau1, out, 0, A3); // 5
    init_kernel<<<8, 256>>>();                                              // 6
    gemm_mma<<<ggrid, 256>>>(A3, B3, 3 * H, nullptr, gi2, 1);               // 7
    scan_kernel<<<NCTA, 512, SCAN_SMEM>>>(gi2, Whh2, bhh2, tau2, out, 256, nullptr); // 8
}

// round 12
// speedup vs baseline: 2.3511x; 1.3389x over previous
#include <cuda_runtime.h>
#include <cuda_bf16.h>
#include <math.h>
#include <stdint.h>

#define D_IN 768
#define H    256
#define NB   64
#define NT   512
#define BT   (NB*NT)    // 32768
#define G3   768        // 3*H
#define SNC  32         // scan CTAs (each owns 8 h-columns)
#define SNT  256        // scan threads

// ---------------- scratch ----------------
__device__ float g_gi1[BT * (size_t)G3];                 // 96 MB time-major (t*64+b)
__device__ float g_gi2[BT * (size_t)G3];                 // 96 MB
__device__ __nv_bfloat16 g_Abuf[BT * (size_t)(3*D_IN)];  // [x_hi|x_lo|x_hi] time-major
__device__ __nv_bfloat16 g_A3[BT * (size_t)(3*H)];       // [h_hi|h_lo|h_hi] time-major
__device__ __nv_bfloat16 g_B1[(size_t)G3 * (3*D_IN)];
__device__ __nv_bfloat16 g_B2[(size_t)G3 * (3*D_IN)];
__device__ __nv_bfloat16 g_B3[(size_t)G3 * (3*H)];
__device__ __nv_bfloat16 g_hsplit[2][NB * 512];          // h state [b][hi(256)|lo(256)]
__device__ __nv_bfloat16 g_Wr1[SNC * 24 * 512];          // per-CTA scan weights [Whi|Wlo]
__device__ __nv_bfloat16 g_Wr2[SNC * 24 * 512];
__device__ unsigned g_cnt;                               // monotonic barrier counter

// ---------------- helpers ----------------
__device__ __forceinline__ uint32_t smem_u32(const void* p) {
    uint32_t a;
    asm("{ .reg .u64 t; cvta.to.shared.u64 t, %1; cvt.u32.u64 %0, t; }" : "=r"(a) : "l"(p));
    return a;
}
__device__ __forceinline__ void ldsm_x4(uint32_t& r0, uint32_t& r1, uint32_t& r2, uint32_t& r3,
                                        uint32_t addr) {
    asm volatile("ldmatrix.sync.aligned.m8n8.x4.shared.b16 {%0,%1,%2,%3}, [%4];"
                 : "=r"(r0), "=r"(r1), "=r"(r2), "=r"(r3) : "r"(addr));
}
__device__ __forceinline__ void ldsm_x2(uint32_t& r0, uint32_t& r1, uint32_t addr) {
    asm volatile("ldmatrix.sync.aligned.m8n8.x2.shared.b16 {%0,%1}, [%2];"
                 : "=r"(r0), "=r"(r1) : "r"(addr));
}
__device__ __forceinline__ void mma_bf16(float* c, const uint32_t* a, const uint32_t* b) {
    asm volatile("mma.sync.aligned.m16n8k16.row.col.f32.bf16.bf16.f32 "
                 "{%0,%1,%2,%3}, {%4,%5,%6,%7}, {%8,%9}, {%0,%1,%2,%3};"
                 : "+f"(c[0]), "+f"(c[1]), "+f"(c[2]), "+f"(c[3])
                 : "r"(a[0]), "r"(a[1]), "r"(a[2]), "r"(a[3]), "r"(b[0]), "r"(b[1]));
}
__device__ __forceinline__ void cp16(uint32_t dst, const void* src) {
    asm volatile("cp.async.cg.shared.global [%0], [%1], 16;" :: "r"(dst), "l"(src));
}
__device__ __forceinline__ void cp_commit() { asm volatile("cp.async.commit_group;"); }
__device__ __forceinline__ void cp_wait1()  { asm volatile("cp.async.wait_group 1;"); }

// gemm smem tile swizzle (64B rows, proven)
__device__ __forceinline__ uint32_t sw_off(int row, int c) {
    return ((uint32_t)row << 6) + (((uint32_t)(c ^ ((row >> 1) & 3))) << 4);
}
// scan smem tile swizzle (1024B rows, 16B chunks)
__device__ __forceinline__ uint32_t sw1k(int row, int c) {
    return ((uint32_t)row << 10) + (((uint32_t)(c ^ (row & 7))) << 4);
}
__device__ __forceinline__ float sigmoidf_(float x) {
    return 1.0f / (1.0f + __expf(-x));
}

// ---------------- prep kernels ----------------
__global__ void prepA_kernel(const float* __restrict__ x, __nv_bfloat16* __restrict__ A) {
    long i = (long)blockIdx.x * blockDim.x + threadIdx.x;
    if (i >= (long)BT * D_IN) return;
    int k = (int)(i % D_IN);
    long row = i / D_IN;              // b*512 + t
    int b = (int)(row >> 9), t = (int)(row & 511);
    float v = x[i];
    __nv_bfloat16 hi = __float2bfloat16(v);
    __nv_bfloat16 lo = __float2bfloat16(v - __bfloat162float(hi));
    long orow = ((long)t * 64 + b) * (3 * D_IN);
    A[orow + k] = hi;
    A[orow + D_IN + k] = lo;
    A[orow + 2 * D_IN + k] = hi;
}

__device__ __forceinline__ void prep_one(const float* __restrict__ W, int Kin,
                                         __nv_bfloat16* __restrict__ Bm, long idx) {
    int n = (int)(idx / Kin), k = (int)(idx % Kin);
    float v = W[(size_t)k * G3 + n];
    __nv_bfloat16 hi = __float2bfloat16(v);
    __nv_bfloat16 lo = __float2bfloat16(v - __bfloat162float(hi));
    size_t o = (size_t)n * (3 * Kin);
    Bm[o + k] = hi;
    Bm[o + Kin + k] = hi;
    Bm[o + 2 * Kin + k] = lo;
}

__global__ void prepB_all(const float* __restrict__ W1, const float* __restrict__ W2,
                          const float* __restrict__ W3,
                          __nv_bfloat16* __restrict__ B1, __nv_bfloat16* __restrict__ B2,
                          __nv_bfloat16* __restrict__ B3) {
    long i = (long)blockIdx.x * blockDim.x + threadIdx.x;
    const long n1 = (long)G3 * D_IN;
    const long n3 = (long)G3 * H;
    if (i < n1)               prep_one(W1, D_IN, B1, i);
    else if (i < 2 * n1)      prep_one(W2, D_IN, B2, i - n1);
    else if (i < 2 * n1 + n3) prep_one(W3, H,    B3, i - 2 * n1);
}

// per-CTA scan weights: dst[cb][n][k'] ; n = g*8+j -> W_hh[k][g*256 + cb*8 + j]
// k'<256 -> hi, k'>=256 -> lo.  Also zero h state + barrier counter.
__global__ void prepWhh(const float* __restrict__ Whh, __nv_bfloat16* __restrict__ dst) {
    long i = (long)blockIdx.x * blockDim.x + threadIdx.x;
    if (i < 2L * NB * 512) ((__nv_bfloat16*)g_hsplit)[i] = __float2bfloat16(0.0f);
    if (i == 0) g_cnt = 0u;
    if (i >= (long)SNC * 24 * 512) return;
    int cb = (int)(i / (24 * 512));
    int rem = (int)(i % (24 * 512));
    int nn = rem / 512, k2 = rem % 512;
    int g = nn >> 3, j = nn & 7;
    int wcol = g * 256 + cb * 8 + j;
    float v = Whh[(size_t)(k2 & 255) * G3 + wcol];
    __nv_bfloat16 hi = __float2bfloat16(v);
    dst[i] = (k2 < 256) ? hi : __float2bfloat16(v - __bfloat162float(hi));
}

// ---------------- HMMA GEMM (unchanged, proven) ----------------
__global__ void __launch_bounds__(256)
gemm_mma(const __nv_bfloat16* __restrict__ A, const __nv_bfloat16* __restrict__ Bm,
         int K, const float* __restrict__ bias, float* __restrict__ C, int acc)
{
    __shared__ __align__(1024) char smA[2][8192];
    __shared__ __align__(1024) char smB[2][8192];

    const int tid = threadIdx.x;
    const int wid = tid >> 5, lid = tid & 31;
    const int warp_m = wid & 3, warp_n = wid >> 2;
    const int m0 = blockIdx.y * 128, n0 = blockIdx.x * 128;

    const __nv_bfloat16* Ag = A + (size_t)m0 * K;
    const __nv_bfloat16* Bg = Bm + (size_t)n0 * K;

    const uint32_t sA[2] = { smem_u32(smA[0]), smem_u32(smA[1]) };
    const uint32_t sB[2] = { smem_u32(smB[0]), smem_u32(smB[1]) };

    const int lrow0 = tid >> 2;
    const int lc    = tid & 3;
    const uint32_t loff0 = sw_off(lrow0, lc);
    const uint32_t loff1 = sw_off(lrow0 + 64, lc);

    float accf[2][8][4];
#pragma unroll
    for (int i = 0; i < 2; i++)
#pragma unroll
        for (int j = 0; j < 8; j++)
#pragma unroll
            for (int q = 0; q < 4; q++) accf[i][j][q] = 0.0f;

    const int nk = K >> 5;

    {
        const char* ga0 = (const char*)(Ag + (size_t)lrow0 * K + lc * 8);
        const char* ga1 = (const char*)(Ag + (size_t)(lrow0 + 64) * K + lc * 8);
        const char* gb0 = (const char*)(Bg + (size_t)lrow0 * K + lc * 8);
        const char* gb1 = (const char*)(Bg + (size_t)(lrow0 + 64) * K + lc * 8);
        cp16(sA[0] + loff0, ga0); cp16(sA[0] + loff1, ga1);
        cp16(sB[0] + loff0, gb0); cp16(sB[0] + loff1, gb1);
        cp_commit();
    }

    const int a_row = (lid & 15);
    const int a_cd  = (lid >> 4);
    const int b_row = (lid & 7) + ((lid >> 4) & 1) * 8;
    const int b_cd  = (lid >> 3) & 1;

    for (int kc = 0; kc < nk; kc++) {
        if (kc + 1 < nk) {
            int koff = (kc + 1) * 32;
            int st = (kc + 1) & 1;
            const char* ga0 = (const char*)(Ag + (size_t)lrow0 * K + koff + lc * 8);
            const char* ga1 = (const char*)(Ag + (size_t)(lrow0 + 64) * K + koff + lc * 8);
            const char* gb0 = (const char*)(Bg + (size_t)lrow0 * K + koff + lc * 8);
            const char* gb1 = (const char*)(Bg + (size_t)(lrow0 + 64) * K + koff + lc * 8);
            cp16(sA[st] + loff0, ga0); cp16(sA[st] + loff1, ga1);
            cp16(sB[st] + loff0, gb0); cp16(sB[st] + loff1, gb1);
        }
        cp_commit();
        cp_wait1();
        __syncthreads();

        const uint32_t aT = sA[kc & 1], bT = sB[kc & 1];
#pragma unroll
        for (int ks = 0; ks < 2; ks++) {
            uint32_t afr[2][4];
#pragma unroll
            for (int fm = 0; fm < 2; fm++) {
                int row = warp_m * 32 + fm * 16 + a_row;
                ldsm_x4(afr[fm][0], afr[fm][1], afr[fm][2], afr[fm][3],
                        aT + sw_off(row, 2 * ks + a_cd));
            }
            uint32_t bfr[8][2];
#pragma unroll
            for (int ng = 0; ng < 4; ng++) {
                int row = warp_n * 64 + ng * 16 + b_row;
                uint32_t r0, r1, r2, r3;
                ldsm_x4(r0, r1, r2, r3, bT + sw_off(row, 2 * ks + b_cd));
                bfr[ng * 2][0] = r0;     bfr[ng * 2][1] = r1;
                bfr[ng * 2 + 1][0] = r2; bfr[ng * 2 + 1][1] = r3;
            }
#pragma unroll
            for (int fm = 0; fm < 2; fm++)
#pragma unroll
                for (int fn = 0; fn < 8; fn++)
                    mma_bf16(accf[fm][fn], afr[fm], bfr[fn]);
        }
        __syncthreads();
    }

#pragma unroll
    for (int fm = 0; fm < 2; fm++) {
        int row = m0 + warp_m * 32 + fm * 16 + (lid >> 2);
#pragma unroll
        for (int fn = 0; fn < 8; fn++) {
            int colg = n0 + warp_n * 64 + fn * 8 + (lid & 3) * 2;
            float2 v0 = make_float2(accf[fm][fn][0], accf[fm][fn][1]);
            float2 v1 = make_float2(accf[fm][fn][2], accf[fm][fn][3]);
            if (bias) {
                float b0 = bias[colg], b1 = bias[colg + 1];
                v0.x += b0; v0.y += b1; v1.x += b0; v1.y += b1;
            }
            float* p0 = C + (size_t)row * G3 + colg;
            float* p1 = C + (size_t)(row + 8) * G3 + colg;
            if (acc) {
                float2 o0 = *(const float2*)p0;
                float2 o1 = *(const float2*)p1;
                v0.x += o0.x; v0.y += o0.y; v1.x += o1.x; v1.y += o1.y;
            }
            *(float2*)p0 = v0;
            *(float2*)p1 = v1;
        }
    }
}

// ---------------- tensor-core persistent scan ----------------
// 32 CTAs x 256 thr. CTA cb owns h-cols c0..c0+7 (c0 = 8*cb) -> 24 weight cols.
// fp32 leaky-integration carry lives in REGISTERS (each thread owns its (b, col
// pair) for the whole scan); split-bf16 h goes to global only as MMA operand.
#define AS_OFF   0
#define BS_OFF   65536
#define GI_OFF   90112
#define PART_OFF 102400
#define SCAN_SMEM 114688

__global__ void __launch_bounds__(SNT, 1)
scan_tc(const float* __restrict__ gi, const __nv_bfloat16* __restrict__ Wsc,
        const float* __restrict__ bhh, const float* __restrict__ tau,
        float* __restrict__ out, int outc0, __nv_bfloat16* __restrict__ a3)
{
    extern __shared__ char sm[];
    const uint32_t as_u = smem_u32(sm + AS_OFF);
    const uint32_t bs_u = smem_u32(sm + BS_OFF);
    const uint32_t gi_u = smem_u32(sm + GI_OFF);
    float* gif  = (float*)(sm + GI_OFF);
    float* part = (float*)(sm + PART_OFF);

    const int cb  = blockIdx.x;
    const int tid = threadIdx.x;
    const int wid = tid >> 5, lid = tid & 31;
    const int c0  = cb * 8;
    const int wm  = wid & 3;          // M-tile (16 rows)
    const int khh = wid >> 2;         // k-half

    // epilogue mapping: thread -> (b, col pair); FIXED across steps
    const int eb = tid >> 2;
    const int ej = (tid & 3) * 2;

    float bias[6];
#pragma unroll
    for (int g = 0; g < 3; g++)
#pragma unroll
        for (int d = 0; d < 2; d++)
            bias[g * 2 + d] = bhh[g * 256 + c0 + ej + d];
    const float invt = 1.0f / tau[0];

    float hold2[2] = {0.0f, 0.0f};    // exact fp32 recurrent carry

    // stationary weights -> smem
    for (int i = tid; i < 1536; i += SNT) {
        int n = i >> 6, c = i & 63;
        cp16(bs_u + sw1k(n, c), Wsc + (size_t)cb * 24 * 512 + n * 512 + c * 8);
    }
    // gi[0] prefetch
    for (int i = tid; i < 384; i += SNT) {
        int b = i / 6, rem = i % 6, g = rem >> 1, hf = rem & 1;
        cp16(gi_u + (uint32_t)(b * 96 + g * 32 + hf * 16),
             gi + ((size_t)b) * G3 + g * 256 + c0 + hf * 4);
    }
    cp_commit();

    for (int t = 0; t < NT; t++) {
        const int cur = t & 1, nxt = cur ^ 1;
        const __nv_bfloat16* hsrc = g_hsplit[cur];

        // fill A (h split) : 4096 chunks
#pragma unroll
        for (int n = 0; n < 16; n++) {
            int F = n * SNT + tid;
            int row = F >> 6, c = F & 63;
            cp16(as_u + sw1k(row, c), hsrc + row * 512 + c * 8);
        }
        cp_commit();
        if (t + 1 < NT) {
            for (int i = tid; i < 384; i += SNT) {
                int b = i / 6, rem = i % 6, g = rem >> 1, hf = rem & 1;
                cp16(gi_u + (uint32_t)(nxt * 6144 + b * 96 + g * 32 + hf * 16),
                     gi + ((size_t)(t + 1) * 64 + b) * G3 + g * 256 + c0 + hf * 4);
            }
        }
        cp_commit();
        cp_wait1();           // A + gi[t] ready; gi[t+1] in flight
        __syncthreads();

        // MMA: 3 products (hi*Whi, lo*Whi, hi*Wlo) x 3 n-tiles x 8 kt
        float cf[3][4];
#pragma unroll
        for (int nt = 0; nt < 3; nt++)
#pragma unroll
            for (int q = 0; q < 4; q++) cf[nt][q] = 0.0f;

        const int a_row = wm * 16 + (lid & 15);
        const int a_cd  = lid >> 4;
        const int b_row4 = (lid & 7) + ((lid >> 4) & 1) * 8;
        const int b_row2 = 16 + (lid & 7);
        const int b_cd   = (lid >> 3) & 1;

#pragma unroll
        for (int ii = 0; ii < 8; ii++) {
            int kt = khh * 8 + ii;
            uint32_t aH[4], aL[4];
            ldsm_x4(aH[0], aH[1], aH[2], aH[3], as_u + sw1k(a_row, 2 * kt + a_cd));
            ldsm_x4(aL[0], aL[1], aL[2], aL[3], as_u + sw1k(a_row, 2 * (16 + kt) + a_cd));
            uint32_t bH[3][2], bL[3][2];
            {
                uint32_t r0, r1, r2, r3;
                ldsm_x4(r0, r1, r2, r3, bs_u + sw1k(b_row4, 2 * kt + b_cd));
                bH[0][0] = r0; bH[0][1] = r1; bH[1][0] = r2; bH[1][1] = r3;
                ldsm_x2(r0, r1, bs_u + sw1k(b_row2, 2 * kt + b_cd));
                bH[2][0] = r0; bH[2][1] = r1;
                ldsm_x4(r0, r1, r2, r3, bs_u + sw1k(b_row4, 2 * (16 + kt) + b_cd));
                bL[0][0] = r0; bL[0][1] = r1; bL[1][0] = r2; bL[1][1] = r3;
                ldsm_x2(r0, r1, bs_u + sw1k(b_row2, 2 * (16 + kt) + b_cd));
                bL[2][0] = r0; bL[2][1] = r1;
            }
#pragma unroll
            for (int nt = 0; nt < 3; nt++) {
                mma_bf16(cf[nt], aH, bH[nt]);
                mma_bf16(cf[nt], aL, bH[nt]);
                mma_bf16(cf[nt], aH, bL[nt]);
            }
        }

        // exchange partials: part[khh][row][24]
#pragma unroll
        for (int nt = 0; nt < 3; nt++) {
            int r0 = wm * 16 + (lid >> 2);
            int cc = nt * 8 + (lid & 3) * 2;
            *(float2*)&part[(khh * 64 + r0) * 24 + cc]     = make_float2(cf[nt][0], cf[nt][1]);
            *(float2*)&part[(khh * 64 + r0 + 8) * 24 + cc] = make_float2(cf[nt][2], cf[nt][3]);
        }
        __syncthreads();

        // gates: thread -> (eb, cols c0+ej, c0+ej+1); carry from registers
        {
            const float* p0 = part + eb * 24;
            const float* p1 = part + (64 + eb) * 24;
            const float* gs = gif + cur * 1536 + eb * 24;
            float hnew2[2];
#pragma unroll
            for (int d = 0; d < 2; d++) {
                int j = ej + d;
                float sr = p0[j] + p1[j];
                float sz = p0[8 + j] + p1[8 + j];
                float sn = p0[16 + j] + p1[16 + j];
                float r = sigmoidf_(gs[j] + sr + bias[d]);
                float z = sigmoidf_(gs[8 + j] + sz + bias[2 + d]);
                float n = tanhf(gs[16 + j] + r * (sn + bias[4 + d]));
                float hold = hold2[d];
                float hc = (1.0f - z) * n + z * hold;
                hnew2[d] = hold + invt * (hc - hold);
                hold2[d] = hnew2[d];
            }
            __nv_bfloat162 nh, nl;
            nh.x = __float2bfloat16(hnew2[0]);
            nh.y = __float2bfloat16(hnew2[1]);
            nl.x = __float2bfloat16(hnew2[0] - __bfloat162float(nh.x));
            nl.y = __float2bfloat16(hnew2[1] - __bfloat162float(nh.y));
            __nv_bfloat16* hd = g_hsplit[nxt] + eb * 512 + c0 + ej;
            *(uint32_t*)hd          = *(uint32_t*)&nh;
            *(uint32_t*)(hd + 256)  = *(uint32_t*)&nl;
            *(float2*)(out + ((size_t)eb * NT + t) * 512 + outc0 + c0 + ej) =
                make_float2(hnew2[0], hnew2[1]);
            if (a3) {
                __nv_bfloat16* ad = a3 + ((size_t)t * 64 + eb) * (3 * H) + c0 + ej;
                *(uint32_t*)ad         = *(uint32_t*)&nh;
                *(uint32_t*)(ad + 256) = *(uint32_t*)&nl;
                *(uint32_t*)(ad + 512) = *(uint32_t*)&nh;
            }
        }
        __threadfence();
        __syncthreads();

        // REDG arrival + single-poller monotonic barrier
        if (tid == 0) {
            asm volatile("red.release.gpu.global.add.u32 [%0], %1;"
                         :: "l"(&g_cnt), "r"(1u) : "memory");
            unsigned tgt = (unsigned)SNC * (unsigned)(t + 1);
            unsigned v;
            do {
                asm volatile("ld.acquire.gpu.global.u32 %0, [%1];"
                             : "=r"(v) : "l"(&g_cnt) : "memory");
            } while (v < tgt);
        }
        __syncthreads();
    }
}

// ---------------- launch ----------------
extern "C" void kernel_launch(void* const* d_in, const int* in_sizes, int n_in,
                              void* d_out, int out_size) {
    const float* x    = (const float*)d_in[0];
    const float* tau1 = (const float*)d_in[1];
    const float* tau2 = (const float*)d_in[2];
    const float* Wih1 = (const float*)d_in[3];
    const float* Whh1 = (const float*)d_in[4];
    const float* bih1 = (const float*)d_in[5];
    const float* bhh1 = (const float*)d_in[6];
    const float* Wih2 = (const float*)d_in[7];
    const float* Whh2 = (const float*)d_in[8];
    const float* bih2 = (const float*)d_in[9];
    const float* bhh2 = (const float*)d_in[10];
    float* out = (float*)d_out;

    float *gi1, *gi2;
    __nv_bfloat16 *Ab, *A3, *B1, *B2, *B3, *Wr1, *Wr2;
    cudaGetSymbolAddress((void**)&gi1, g_gi1);
    cudaGetSymbolAddress((void**)&gi2, g_gi2);
    cudaGetSymbolAddress((void**)&Ab,  g_Abuf);
    cudaGetSymbolAddress((void**)&A3,  g_A3);
    cudaGetSymbolAddress((void**)&B1,  g_B1);
    cudaGetSymbolAddress((void**)&B2,  g_B2);
    cudaGetSymbolAddress((void**)&B3,  g_B3);
    cudaGetSymbolAddress((void**)&Wr1, g_Wr1);
    cudaGetSymbolAddress((void**)&Wr2, g_Wr2);

    cudaFuncSetAttribute(scan_tc,
                         cudaFuncAttributeMaxDynamicSharedMemorySize, SCAN_SMEM);

    dim3 ggrid(G3 / 128, BT / 128);   // (6, 256)
    int wgrid = (SNC * 24 * 512 + 255) / 256;

    prepA_kernel<<<(int)(((long)BT * D_IN + 255) / 256), 256>>>(x, Ab);        // 0
    {
        long tot = 2L * G3 * D_IN + (long)G3 * H;
        prepB_all<<<(int)((tot + 255) / 256), 256>>>(
            Wih1, Wih2, Wih2 + (size_t)D_IN * G3, B1, B2, B3);                 // 1
    }
    prepWhh<<<wgrid, 256>>>(Whh1, Wr1);                                        // 2 (+init)
    gemm_mma<<<ggrid, 256>>>(Ab, B1, 3 * D_IN, bih1, gi1, 0);                  // 3
    scan_tc<<<SNC, SNT, SCAN_SMEM>>>(gi1, Wr1, bhh1, tau1, out, 0, A3);        // 4
    prepWhh<<<wgrid, 256>>>(Whh2, Wr2);                                        // 5 (+re-init)
    gemm_mma<<<ggrid, 256>>>(Ab, B2, 3 * D_IN, bih2, gi2, 0);                  // 6
    gemm_mma<<<ggrid, 256>>>(A3, B3, 3 * H, nullptr, gi2, 1);                  // 7
    scan_tc<<<SNC, SNT, SCAN_SMEM>>>(gi2, Wr2, bhh2, tau2, out, 256, nullptr); // 8
}

// round 13
// speedup vs baseline: 2.6954x; 1.1465x over previous
#include <cuda_runtime.h>
#include <cuda_bf16.h>
#include <math.h>
#include <stdint.h>

#define D_IN 768
#define H    256
#define NB   64
#define NT   512
#define BT   (NB*NT)    // 32768
#define G3   768        // 3*H
#define SNC  32         // scan CTAs (each owns 8 h-columns)
#define SNT  256        // scan threads

// ---------------- scratch ----------------
__device__ float g_gi1[BT * (size_t)G3];                 // 96 MB time-major (t*64+b)
__device__ float g_gi2[BT * (size_t)G3];                 // 96 MB
__device__ __nv_bfloat16 g_Abuf[BT * (size_t)(3*D_IN)];  // [x_hi|x_lo|x_hi] time-major
__device__ __nv_bfloat16 g_A3[BT * (size_t)(3*H)];       // [h_hi|h_lo|h_hi] time-major
__device__ __nv_bfloat16 g_B1[(size_t)G3 * (3*D_IN)];
__device__ __nv_bfloat16 g_B2[(size_t)G3 * (3*D_IN)];
__device__ __nv_bfloat16 g_B3[(size_t)G3 * (3*H)];
__device__ __nv_bfloat16 g_hsplit[2][NB * 512];          // h state [b][hi(256)|lo(256)]
__device__ __nv_bfloat16 g_Wr1[SNC * 24 * 512];          // per-CTA scan weights [Whi|Wlo]
__device__ __nv_bfloat16 g_Wr2[SNC * 24 * 512];
__device__ unsigned g_cnt;                               // monotonic barrier counter

// ---------------- helpers ----------------
__device__ __forceinline__ uint32_t smem_u32(const void* p) {
    uint32_t a;
    asm("{ .reg .u64 t; cvta.to.shared.u64 t, %1; cvt.u32.u64 %0, t; }" : "=r"(a) : "l"(p));
    return a;
}
__device__ __forceinline__ void ldsm_x4(uint32_t& r0, uint32_t& r1, uint32_t& r2, uint32_t& r3,
                                        uint32_t addr) {
    asm volatile("ldmatrix.sync.aligned.m8n8.x4.shared.b16 {%0,%1,%2,%3}, [%4];"
                 : "=r"(r0), "=r"(r1), "=r"(r2), "=r"(r3) : "r"(addr));
}
__device__ __forceinline__ void ldsm_x2(uint32_t& r0, uint32_t& r1, uint32_t addr) {
    asm volatile("ldmatrix.sync.aligned.m8n8.x2.shared.b16 {%0,%1}, [%2];"
                 : "=r"(r0), "=r"(r1) : "r"(addr));
}
__device__ __forceinline__ void mma_bf16(float* c, const uint32_t* a, const uint32_t* b) {
    asm volatile("mma.sync.aligned.m16n8k16.row.col.f32.bf16.bf16.f32 "
                 "{%0,%1,%2,%3}, {%4,%5,%6,%7}, {%8,%9}, {%0,%1,%2,%3};"
                 : "+f"(c[0]), "+f"(c[1]), "+f"(c[2]), "+f"(c[3])
                 : "r"(a[0]), "r"(a[1]), "r"(a[2]), "r"(a[3]), "r"(b[0]), "r"(b[1]));
}
__device__ __forceinline__ void cp16(uint32_t dst, const void* src) {
    asm volatile("cp.async.cg.shared.global [%0], [%1], 16;" :: "r"(dst), "l"(src));
}
__device__ __forceinline__ void cp_commit() { asm volatile("cp.async.commit_group;"); }
__device__ __forceinline__ void cp_wait1()  { asm volatile("cp.async.wait_group 1;"); }
__device__ __forceinline__ void cp_wait0()  { asm volatile("cp.async.wait_group 0;"); }

// gemm smem tile swizzle (64B rows, proven)
__device__ __forceinline__ uint32_t sw_off(int row, int c) {
    return ((uint32_t)row << 6) + (((uint32_t)(c ^ ((row >> 1) & 3))) << 4);
}
// scan smem tile swizzle (1024B rows, 16B chunks)
__device__ __forceinline__ uint32_t sw1k(int row, int c) {
    return ((uint32_t)row << 10) + (((uint32_t)(c ^ (row & 7))) << 4);
}
__device__ __forceinline__ float sigmoidf_(float x) {
    return 1.0f / (1.0f + __expf(-x));
}
__device__ __forceinline__ float tanhf_(float x) {
    float e = __expf(-2.0f * x);
    return (1.0f - e) / (1.0f + e);
}

// ---------------- prep kernels ----------------
__global__ void prepA_kernel(const float* __restrict__ x, __nv_bfloat16* __restrict__ A) {
    long i = (long)blockIdx.x * blockDim.x + threadIdx.x;
    if (i >= (long)BT * D_IN) return;
    int k = (int)(i % D_IN);
    long row = i / D_IN;              // b*512 + t
    int b = (int)(row >> 9), t = (int)(row & 511);
    float v = x[i];
    __nv_bfloat16 hi = __float2bfloat16(v);
    __nv_bfloat16 lo = __float2bfloat16(v - __bfloat162float(hi));
    long orow = ((long)t * 64 + b) * (3 * D_IN);
    A[orow + k] = hi;
    A[orow + D_IN + k] = lo;
    A[orow + 2 * D_IN + k] = hi;
}

__device__ __forceinline__ void prep_one(const float* __restrict__ W, int Kin,
                                         __nv_bfloat16* __restrict__ Bm, long idx) {
    int n = (int)(idx / Kin), k = (int)(idx % Kin);
    float v = W[(size_t)k * G3 + n];
    __nv_bfloat16 hi = __float2bfloat16(v);
    __nv_bfloat16 lo = __float2bfloat16(v - __bfloat162float(hi));
    size_t o = (size_t)n * (3 * Kin);
    Bm[o + k] = hi;
    Bm[o + Kin + k] = hi;
    Bm[o + 2 * Kin + k] = lo;
}

__global__ void prepB_all(const float* __restrict__ W1, const float* __restrict__ W2,
                          const float* __restrict__ W3,
                          __nv_bfloat16* __restrict__ B1, __nv_bfloat16* __restrict__ B2,
                          __nv_bfloat16* __restrict__ B3) {
    long i = (long)blockIdx.x * blockDim.x + threadIdx.x;
    const long n1 = (long)G3 * D_IN;
    const long n3 = (long)G3 * H;
    if (i < n1)               prep_one(W1, D_IN, B1, i);
    else if (i < 2 * n1)      prep_one(W2, D_IN, B2, i - n1);
    else if (i < 2 * n1 + n3) prep_one(W3, H,    B3, i - 2 * n1);
}

// per-CTA scan weights + zero h state + reset barrier counter
__global__ void prepWhh(const float* __restrict__ Whh, __nv_bfloat16* __restrict__ dst) {
    long i = (long)blockIdx.x * blockDim.x + threadIdx.x;
    if (i < 2L * NB * 512) ((__nv_bfloat16*)g_hsplit)[i] = __float2bfloat16(0.0f);
    if (i == 0) g_cnt = 0u;
    if (i >= (long)SNC * 24 * 512) return;
    int cb = (int)(i / (24 * 512));
    int rem = (int)(i % (24 * 512));
    int nn = rem / 512, k2 = rem % 512;
    int g = nn >> 3, j = nn & 7;
    int wcol = g * 256 + cb * 8 + j;
    float v = Whh[(size_t)(k2 & 255) * G3 + wcol];
    __nv_bfloat16 hi = __float2bfloat16(v);
    dst[i] = (k2 < 256) ? hi : __float2bfloat16(v - __bfloat162float(hi));
}

// ---------------- HMMA GEMM (unchanged, proven) ----------------
__global__ void __launch_bounds__(256)
gemm_mma(const __nv_bfloat16* __restrict__ A, const __nv_bfloat16* __restrict__ Bm,
         int K, const float* __restrict__ bias, float* __restrict__ C, int acc)
{
    __shared__ __align__(1024) char smA[2][8192];
    __shared__ __align__(1024) char smB[2][8192];

    const int tid = threadIdx.x;
    const int wid = tid >> 5, lid = tid & 31;
    const int warp_m = wid & 3, warp_n = wid >> 2;
    const int m0 = blockIdx.y * 128, n0 = blockIdx.x * 128;

    const __nv_bfloat16* Ag = A + (size_t)m0 * K;
    const __nv_bfloat16* Bg = Bm + (size_t)n0 * K;

    const uint32_t sA[2] = { smem_u32(smA[0]), smem_u32(smA[1]) };
    const uint32_t sB[2] = { smem_u32(smB[0]), smem_u32(smB[1]) };

    const int lrow0 = tid >> 2;
    const int lc    = tid & 3;
    const uint32_t loff0 = sw_off(lrow0, lc);
    const uint32_t loff1 = sw_off(lrow0 + 64, lc);

    float accf[2][8][4];
#pragma unroll
    for (int i = 0; i < 2; i++)
#pragma unroll
        for (int j = 0; j < 8; j++)
#pragma unroll
            for (int q = 0; q < 4; q++) accf[i][j][q] = 0.0f;

    const int nk = K >> 5;

    {
        const char* ga0 = (const char*)(Ag + (size_t)lrow0 * K + lc * 8);
        const char* ga1 = (const char*)(Ag + (size_t)(lrow0 + 64) * K + lc * 8);
        const char* gb0 = (const char*)(Bg + (size_t)lrow0 * K + lc * 8);
        const char* gb1 = (const char*)(Bg + (size_t)(lrow0 + 64) * K + lc * 8);
        cp16(sA[0] + loff0, ga0); cp16(sA[0] + loff1, ga1);
        cp16(sB[0] + loff0, gb0); cp16(sB[0] + loff1, gb1);
        cp_commit();
    }

    const int a_row = (lid & 15);
    const int a_cd  = (lid >> 4);
    const int b_row = (lid & 7) + ((lid >> 4) & 1) * 8;
    const int b_cd  = (lid >> 3) & 1;

    for (int kc = 0; kc < nk; kc++) {
        if (kc + 1 < nk) {
            int koff = (kc + 1) * 32;
            int st = (kc + 1) & 1;
            const char* ga0 = (const char*)(Ag + (size_t)lrow0 * K + koff + lc * 8);
            const char* ga1 = (const char*)(Ag + (size_t)(lrow0 + 64) * K + koff + lc * 8);
            const char* gb0 = (const char*)(Bg + (size_t)lrow0 * K + koff + lc * 8);
            const char* gb1 = (const char*)(Bg + (size_t)(lrow0 + 64) * K + koff + lc * 8);
            cp16(sA[st] + loff0, ga0); cp16(sA[st] + loff1, ga1);
            cp16(sB[st] + loff0, gb0); cp16(sB[st] + loff1, gb1);
        }
        cp_commit();
        cp_wait1();
        __syncthreads();

        const uint32_t aT = sA[kc & 1], bT = sB[kc & 1];
#pragma unroll
        for (int ks = 0; ks < 2; ks++) {
            uint32_t afr[2][4];
#pragma unroll
            for (int fm = 0; fm < 2; fm++) {
                int row = warp_m * 32 + fm * 16 + a_row;
                ldsm_x4(afr[fm][0], afr[fm][1], afr[fm][2], afr[fm][3],
                        aT + sw_off(row, 2 * ks + a_cd));
            }
            uint32_t bfr[8][2];
#pragma unroll
            for (int ng = 0; ng < 4; ng++) {
                int row = warp_n * 64 + ng * 16 + b_row;
                uint32_t r0, r1, r2, r3;
                ldsm_x4(r0, r1, r2, r3, bT + sw_off(row, 2 * ks + b_cd));
                bfr[ng * 2][0] = r0;     bfr[ng * 2][1] = r1;
                bfr[ng * 2 + 1][0] = r2; bfr[ng * 2 + 1][1] = r3;
            }
#pragma unroll
            for (int fm = 0; fm < 2; fm++)
#pragma unroll
                for (int fn = 0; fn < 8; fn++)
                    mma_bf16(accf[fm][fn], afr[fm], bfr[fn]);
        }
        __syncthreads();
    }

#pragma unroll
    for (int fm = 0; fm < 2; fm++) {
        int row = m0 + warp_m * 32 + fm * 16 + (lid >> 2);
#pragma unroll
        for (int fn = 0; fn < 8; fn++) {
            int colg = n0 + warp_n * 64 + fn * 8 + (lid & 3) * 2;
            float2 v0 = make_float2(accf[fm][fn][0], accf[fm][fn][1]);
            float2 v1 = make_float2(accf[fm][fn][2], accf[fm][fn][3]);
            if (bias) {
                float b0 = bias[colg], b1 = bias[colg + 1];
                v0.x += b0; v0.y += b1; v1.x += b0; v1.y += b1;
            }
            float* p0 = C + (size_t)row * G3 + colg;
            float* p1 = C + (size_t)(row + 8) * G3 + colg;
            if (acc) {
                float2 o0 = *(const float2*)p0;
                float2 o1 = *(const float2*)p1;
                v0.x += o0.x; v0.y += o0.y; v1.x += o1.x; v1.y += o1.y;
            }
            *(float2*)p0 = v0;
            *(float2*)p1 = v1;
        }
    }
}

// ---------------- tensor-core persistent scan (v2) ----------------
// 32 CTAs x 256 thr. CTA cb owns h-cols c0..c0+7 -> 24 weight cols.
// Warp-local A fill (disjoint 8KB per warp, no CTA sync before MMA),
// register-resident stationary B fragments, register gi prefetch,
// fp32 register carry, barrier without per-thread membar.
#define AS_OFF   0
#define BS_OFF   65536
#define PART_OFF 90112
#define SCAN_SMEM 102400

__global__ void __launch_bounds__(SNT, 1)
scan_tc(const float* __restrict__ gi, const __nv_bfloat16* __restrict__ Wsc,
        const float* __restrict__ bhh, const float* __restrict__ tau,
        float* __restrict__ out, int outc0, __nv_bfloat16* __restrict__ a3)
{
    extern __shared__ char sm[];
    const uint32_t as_u = smem_u32(sm + AS_OFF);
    const uint32_t bs_u = smem_u32(sm + BS_OFF);
    float* part = (float*)(sm + PART_OFF);

    const int cb  = blockIdx.x;
    const int tid = threadIdx.x;
    const int wid = tid >> 5, lid = tid & 31;
    const int c0  = cb * 8;
    const int wm  = wid & 3;          // M-tile (16 rows)
    const int khh = wid >> 2;         // k-half

    const int eb = tid >> 2;          // epilogue batch row
    const int ej = (tid & 3) * 2;     // epilogue col pair

    float bias[6];
#pragma unroll
    for (int g = 0; g < 3; g++)
#pragma unroll
        for (int d = 0; d < 2; d++)
            bias[g * 2 + d] = bhh[g * 256 + c0 + ej + d];
    const float invt = 1.0f / tau[0];
    float hold2[2] = {0.0f, 0.0f};    // exact fp32 recurrent carry

    // stationary weights -> smem (one-time)
    for (int i = tid; i < 1536; i += SNT) {
        int n = i >> 6, c = i & 63;
        cp16(bs_u + sw1k(n, c), Wsc + (size_t)cb * 24 * 512 + n * 512 + c * 8);
    }
    cp_commit();
    cp_wait0();
    __syncthreads();

    // resident B fragments (hoisted out of the t-loop)
    const int b_row4 = (lid & 7) + ((lid >> 4) & 1) * 8;
    const int b_row2 = 16 + (lid & 7);
    const int b_cd   = (lid >> 3) & 1;
    uint32_t bH[8][3][2], bL[8][3][2];
#pragma unroll
    for (int ii = 0; ii < 8; ii++) {
        int kt = khh * 8 + ii;
        uint32_t r0, r1, r2, r3;
        ldsm_x4(r0, r1, r2, r3, bs_u + sw1k(b_row4, 2 * kt + b_cd));
        bH[ii][0][0] = r0; bH[ii][0][1] = r1; bH[ii][1][0] = r2; bH[ii][1][1] = r3;
        ldsm_x2(r0, r1, bs_u + sw1k(b_row2, 2 * kt + b_cd));
        bH[ii][2][0] = r0; bH[ii][2][1] = r1;
        ldsm_x4(r0, r1, r2, r3, bs_u + sw1k(b_row4, 2 * (16 + kt) + b_cd));
        bL[ii][0][0] = r0; bL[ii][0][1] = r1; bL[ii][1][0] = r2; bL[ii][1][1] = r3;
        ldsm_x2(r0, r1, bs_u + sw1k(b_row2, 2 * (16 + kt) + b_cd));
        bL[ii][2][0] = r0; bL[ii][2][1] = r1;
    }

    // gi register prefetch for t=0
    const float* g0 = gi + (size_t)eb * G3 + c0 + ej;
    float2 pr = *(const float2*)(g0);
    float2 pz = *(const float2*)(g0 + 256);
    float2 pn = *(const float2*)(g0 + 512);

    const int a_row = wm * 16 + (lid & 15);
    const int a_cd  = lid >> 4;
    // warp-local fill chunk (disjoint across warps; covers all 64x64 chunks)
    const int fl_c  = (lid < 16) ? (khh * 16 + lid) : (32 + khh * 16 + lid - 16);

    for (int t = 0; t < NT; t++) {
        const int cur = t & 1, nxt = cur ^ 1;
        const __nv_bfloat16* hsrc = g_hsplit[cur];

        // prefetch gi for t+1 (independent; hidden behind MMA)
        int tnn = (t + 1 < NT) ? t + 1 : t;
        const float* gx = gi + ((size_t)tnn * 64 + eb) * G3 + c0 + ej;
        float2 tr = *(const float2*)(gx);
        float2 tz = *(const float2*)(gx + 256);
        float2 tn2 = *(const float2*)(gx + 512);

        // warp-local A fill: 16 rows x this lane's chunk
#pragma unroll
        for (int i = 0; i < 16; i++) {
            int row = wm * 16 + i;
            cp16(as_u + sw1k(row, fl_c), hsrc + row * 512 + fl_c * 8);
        }
        cp_commit();
        cp_wait0();
        __syncwarp();

        // MMA: 3 products x 3 n-tiles x 8 kt (B frags resident)
        float cf[3][4];
#pragma unroll
        for (int nt = 0; nt < 3; nt++)
#pragma unroll
            for (int q = 0; q < 4; q++) cf[nt][q] = 0.0f;

#pragma unroll
        for (int ii = 0; ii < 8; ii++) {
            int kt = khh * 8 + ii;
            uint32_t aH[4], aL[4];
            ldsm_x4(aH[0], aH[1], aH[2], aH[3], as_u + sw1k(a_row, 2 * kt + a_cd));
            ldsm_x4(aL[0], aL[1], aL[2], aL[3], as_u + sw1k(a_row, 2 * (16 + kt) + a_cd));
#pragma unroll
            for (int nt = 0; nt < 3; nt++) {
                mma_bf16(cf[nt], aH, bH[ii][nt]);
                mma_bf16(cf[nt], aL, bH[ii][nt]);
                mma_bf16(cf[nt], aH, bL[ii][nt]);
            }
        }

        // exchange partials: part[khh][row][24]
#pragma unroll
        for (int nt = 0; nt < 3; nt++) {
            int r0 = wm * 16 + (lid >> 2);
            int cc = nt * 8 + (lid & 3) * 2;
            *(float2*)&part[(khh * 64 + r0) * 24 + cc]     = make_float2(cf[nt][0], cf[nt][1]);
            *(float2*)&part[(khh * 64 + r0 + 8) * 24 + cc] = make_float2(cf[nt][2], cf[nt][3]);
        }
        __syncthreads();

        // gates (register carry, register gi)
        {
            const float* p0 = part + eb * 24;
            const float* p1 = part + (64 + eb) * 24;
            float xr[2] = {pr.x, pr.y}, xz[2] = {pz.x, pz.y}, xn[2] = {pn.x, pn.y};
            float hnew2[2];
#pragma unroll
            for (int d = 0; d < 2; d++) {
                int j = ej + d;
                float sr = p0[j] + p1[j];
                float sz = p0[8 + j] + p1[8 + j];
                float sn = p0[16 + j] + p1[16 + j];
                float r = sigmoidf_(xr[d] + sr + bias[d]);
                float z = sigmoidf_(xz[d] + sz + bias[2 + d]);
                float n = tanhf_(xn[d] + r * (sn + bias[4 + d]));
                float hold = hold2[d];
                float hc = (1.0f - z) * n + z * hold;
                hnew2[d] = hold + invt * (hc - hold);
                hold2[d] = hnew2[d];
            }
            __nv_bfloat162 nh, nl;
            nh.x = __float2bfloat16(hnew2[0]);
            nh.y = __float2bfloat16(hnew2[1]);
            nl.x = __float2bfloat16(hnew2[0] - __bfloat162float(nh.x));
            nl.y = __float2bfloat16(hnew2[1] - __bfloat162float(nh.y));
            __nv_bfloat16* hd = g_hsplit[nxt] + eb * 512 + c0 + ej;
            *(uint32_t*)hd          = *(uint32_t*)&nh;
            *(uint32_t*)(hd + 256)  = *(uint32_t*)&nl;
            *(float2*)(out + ((size_t)eb * NT + t) * 512 + outc0 + c0 + ej) =
                make_float2(hnew2[0], hnew2[1]);
            if (a3) {
                __nv_bfloat16* ad = a3 + ((size_t)t * 64 + eb) * (3 * H) + c0 + ej;
                *(uint32_t*)ad         = *(uint32_t*)&nh;
                *(uint32_t*)(ad + 256) = *(uint32_t*)&nl;
                *(uint32_t*)(ad + 512) = *(uint32_t*)&nh;
            }
        }
        __syncthreads();   // all h stores sequenced before tid0's release-arrival

        if (tid == 0) {
            asm volatile("red.release.gpu.global.add.u32 [%0], %1;"
                         :: "l"(&g_cnt), "r"(1u) : "memory");
            unsigned tgt = (unsigned)SNC * (unsigned)(t + 1);
            unsigned v;
            do {
                asm volatile("ld.acquire.gpu.global.u32 %0, [%1];"
                             : "=r"(v) : "l"(&g_cnt) : "memory");
            } while (v < tgt);
        }
        __syncthreads();

        pr = tr; pz = tz; pn = tn2;
    }
}

// ---------------- launch ----------------
extern "C" void kernel_launch(void* const* d_in, const int* in_sizes, int n_in,
                              void* d_out, int out_size) {
    const float* x    = (const float*)d_in[0];
    const float* tau1 = (const float*)d_in[1];
    const float* tau2 = (const float*)d_in[2];
    const float* Wih1 = (const float*)d_in[3];
    const float* Whh1 = (const float*)d_in[4];
    const float* bih1 = (const float*)d_in[5];
    const float* bhh1 = (const float*)d_in[6];
    const float* Wih2 = (const float*)d_in[7];
    const float* Whh2 = (const float*)d_in[8];
    const float* bih2 = (const float*)d_in[9];
    const float* bhh2 = (const float*)d_in[10];
    float* out = (float*)d_out;

    float *gi1, *gi2;
    __nv_bfloat16 *Ab, *A3, *B1, *B2, *B3, *Wr1, *Wr2;
    cudaGetSymbolAddress((void**)&gi1, g_gi1);
    cudaGetSymbolAddress((void**)&gi2, g_gi2);
    cudaGetSymbolAddress((void**)&Ab,  g_Abuf);
    cudaGetSymbolAddress((void**)&A3,  g_A3);
    cudaGetSymbolAddress((void**)&B1,  g_B1);
    cudaGetSymbolAddress((void**)&B2,  g_B2);
    cudaGetSymbolAddress((void**)&B3,  g_B3);
    cudaGetSymbolAddress((void**)&Wr1, g_Wr1);
    cudaGetSymbolAddress((void**)&Wr2, g_Wr2);

    cudaFuncSetAttribute(scan_tc,
                         cudaFuncAttributeMaxDynamicSharedMemorySize, SCAN_SMEM);

    dim3 ggrid(G3 / 128, BT / 128);   // (6, 256)
    int wgrid = (SNC * 24 * 512 + 255) / 256;

    prepA_kernel<<<(int)(((long)BT * D_IN + 255) / 256), 256>>>(x, Ab);        // 0
    {
        long tot = 2L * G3 * D_IN + (long)G3 * H;
        prepB_all<<<(int)((tot + 255) / 256), 256>>>(
            Wih1, Wih2, Wih2 + (size_t)D_IN * G3, B1, B2, B3);                 // 1
    }
    prepWhh<<<wgrid, 256>>>(Whh1, Wr1);                                        // 2 (+init)
    gemm_mma<<<ggrid, 256>>>(Ab, B1, 3 * D_IN, bih1, gi1, 0);                  // 3
    scan_tc<<<SNC, SNT, SCAN_SMEM>>>(gi1, Wr1, bhh1, tau1, out, 0, A3);        // 4
    prepWhh<<<wgrid, 256>>>(Whh2, Wr2);                                        // 5 (+re-init)
    gemm_mma<<<ggrid, 256>>>(Ab, B2, 3 * D_IN, bih2, gi2, 0);                  // 6
    gemm_mma<<<ggrid, 256>>>(A3, B3, 3 * H, nullptr, gi2, 1);                  // 7
    scan_tc<<<SNC, SNT, SCAN_SMEM>>>(gi2, Wr2, bhh2, tau2, out, 256, nullptr); // 8
}

// round 14
// speedup vs baseline: 2.8948x; 1.0740x over previous
#include <cuda_runtime.h>
#include <cuda_bf16.h>
#include <math.h>
#include <stdint.h>

#define D_IN 768
#define H    256
#define NB   64
#define NT   512
#define BT   (NB*NT)    // 32768
#define G3   768        // 3*H
#define SNC  64         // scan CTAs (each owns 4 h-columns)
#define SNT  256        // scan threads

// ---------------- scratch ----------------
__device__ float g_gi1[BT * (size_t)G3];                 // 96 MB time-major (t*64+b)
__device__ float g_gi2[BT * (size_t)G3];                 // 96 MB
__device__ __nv_bfloat16 g_Abuf[BT * (size_t)(3*D_IN)];  // [x_hi|x_lo|x_hi] time-major
__device__ __nv_bfloat16 g_A3[BT * (size_t)(3*H)];       // [h_hi|h_lo|h_hi] time-major
__device__ __nv_bfloat16 g_B1[(size_t)G3 * (3*D_IN)];
__device__ __nv_bfloat16 g_B2[(size_t)G3 * (3*D_IN)];
__device__ __nv_bfloat16 g_B3[(size_t)G3 * (3*H)];
__device__ __nv_bfloat16 g_hsplit[2][NB * 512];          // h state [b][hi(256)|lo(256)]
__device__ __nv_bfloat16 g_Wr1[SNC * 16 * 512];          // per-CTA scan weights [Whi|Wlo], 16 rows (12 used)
__device__ __nv_bfloat16 g_Wr2[SNC * 16 * 512];
__device__ unsigned g_cnt;                               // monotonic barrier counter

// ---------------- helpers ----------------
__device__ __forceinline__ uint32_t smem_u32(const void* p) {
    uint32_t a;
    asm("{ .reg .u64 t; cvta.to.shared.u64 t, %1; cvt.u32.u64 %0, t; }" : "=r"(a) : "l"(p));
    return a;
}
__device__ __forceinline__ void ldsm_x4(uint32_t& r0, uint32_t& r1, uint32_t& r2, uint32_t& r3,
                                        uint32_t addr) {
    asm volatile("ldmatrix.sync.aligned.m8n8.x4.shared.b16 {%0,%1,%2,%3}, [%4];"
                 : "=r"(r0), "=r"(r1), "=r"(r2), "=r"(r3) : "r"(addr));
}
__device__ __forceinline__ void mma_bf16(float* c, const uint32_t* a, const uint32_t* b) {
    asm volatile("mma.sync.aligned.m16n8k16.row.col.f32.bf16.bf16.f32 "
                 "{%0,%1,%2,%3}, {%4,%5,%6,%7}, {%8,%9}, {%0,%1,%2,%3};"
                 : "+f"(c[0]), "+f"(c[1]), "+f"(c[2]), "+f"(c[3])
                 : "r"(a[0]), "r"(a[1]), "r"(a[2]), "r"(a[3]), "r"(b[0]), "r"(b[1]));
}
__device__ __forceinline__ void cp16(uint32_t dst, const void* src) {
    asm volatile("cp.async.cg.shared.global [%0], [%1], 16;" :: "r"(dst), "l"(src));
}
__device__ __forceinline__ void cp_commit() { asm volatile("cp.async.commit_group;"); }
__device__ __forceinline__ void cp_wait1()  { asm volatile("cp.async.wait_group 1;"); }
__device__ __forceinline__ void cp_wait0()  { asm volatile("cp.async.wait_group 0;"); }

// gemm smem tile swizzle (64B rows, proven)
__device__ __forceinline__ uint32_t sw_off(int row, int c) {
    return ((uint32_t)row << 6) + (((uint32_t)(c ^ ((row >> 1) & 3))) << 4);
}
// scan smem tile swizzle (1024B rows, 16B chunks)
__device__ __forceinline__ uint32_t sw1k(int row, int c) {
    return ((uint32_t)row << 10) + (((uint32_t)(c ^ (row & 7))) << 4);
}
__device__ __forceinline__ float sigmoidf_(float x) {
    return 1.0f / (1.0f + __expf(-x));
}
__device__ __forceinline__ float tanhf_(float x) {
    float e = __expf(-2.0f * x);
    return (1.0f - e) / (1.0f + e);
}

// ---------------- prep kernels ----------------
__global__ void prepA_kernel(const float* __restrict__ x, __nv_bfloat16* __restrict__ A) {
    long i = (long)blockIdx.x * blockDim.x + threadIdx.x;
    if (i >= (long)BT * D_IN) return;
    int k = (int)(i % D_IN);
    long row = i / D_IN;              // b*512 + t
    int b = (int)(row >> 9), t = (int)(row & 511);
    float v = x[i];
    __nv_bfloat16 hi = __float2bfloat16(v);
    __nv_bfloat16 lo = __float2bfloat16(v - __bfloat162float(hi));
    long orow = ((long)t * 64 + b) * (3 * D_IN);
    A[orow + k] = hi;
    A[orow + D_IN + k] = lo;
    A[orow + 2 * D_IN + k] = hi;
}

__device__ __forceinline__ void prep_one(const float* __restrict__ W, int Kin,
                                         __nv_bfloat16* __restrict__ Bm, long idx) {
    int n = (int)(idx / Kin), k = (int)(idx % Kin);
    float v = W[(size_t)k * G3 + n];
    __nv_bfloat16 hi = __float2bfloat16(v);
    __nv_bfloat16 lo = __float2bfloat16(v - __bfloat162float(hi));
    size_t o = (size_t)n * (3 * Kin);
    Bm[o + k] = hi;
    Bm[o + Kin + k] = hi;
    Bm[o + 2 * Kin + k] = lo;
}

__global__ void prepB_all(const float* __restrict__ W1, const float* __restrict__ W2,
                          const float* __restrict__ W3,
                          __nv_bfloat16* __restrict__ B1, __nv_bfloat16* __restrict__ B2,
                          __nv_bfloat16* __restrict__ B3) {
    long i = (long)blockIdx.x * blockDim.x + threadIdx.x;
    const long n1 = (long)G3 * D_IN;
    const long n3 = (long)G3 * H;
    if (i < n1)               prep_one(W1, D_IN, B1, i);
    else if (i < 2 * n1)      prep_one(W2, D_IN, B2, i - n1);
    else if (i < 2 * n1 + n3) prep_one(W3, H,    B3, i - 2 * n1);
}

// per-CTA scan weights (16-row tiles, rows 12-15 zero) + zero h + reset barrier
// n = g*4 + j  ->  W_hh[k][g*256 + cb*4 + j]
__global__ void prepWhh(const float* __restrict__ Whh, __nv_bfloat16* __restrict__ dst) {
    long i = (long)blockIdx.x * blockDim.x + threadIdx.x;
    if (i < 2L * NB * 512) ((__nv_bfloat16*)g_hsplit)[i] = __float2bfloat16(0.0f);
    if (i == 0) g_cnt = 0u;
    if (i >= (long)SNC * 16 * 512) return;
    int cb = (int)(i / (16 * 512));
    int rem = (int)(i % (16 * 512));
    int nn = rem / 512, k2 = rem % 512;
    if (nn >= 12) { dst[i] = __float2bfloat16(0.0f); return; }
    int g = nn >> 2, j = nn & 3;
    int wcol = g * 256 + cb * 4 + j;
    float v = Whh[(size_t)(k2 & 255) * G3 + wcol];
    __nv_bfloat16 hi = __float2bfloat16(v);
    dst[i] = (k2 < 256) ? hi : __float2bfloat16(v - __bfloat162float(hi));
}

// ---------------- HMMA GEMM (unchanged, proven) ----------------
__global__ void __launch_bounds__(256)
gemm_mma(const __nv_bfloat16* __restrict__ A, const __nv_bfloat16* __restrict__ Bm,
         int K, const float* __restrict__ bias, float* __restrict__ C, int acc)
{
    __shared__ __align__(1024) char smA[2][8192];
    __shared__ __align__(1024) char smB[2][8192];

    const int tid = threadIdx.x;
    const int wid = tid >> 5, lid = tid & 31;
    const int warp_m = wid & 3, warp_n = wid >> 2;
    const int m0 = blockIdx.y * 128, n0 = blockIdx.x * 128;

    const __nv_bfloat16* Ag = A + (size_t)m0 * K;
    const __nv_bfloat16* Bg = Bm + (size_t)n0 * K;

    const uint32_t sA[2] = { smem_u32(smA[0]), smem_u32(smA[1]) };
    const uint32_t sB[2] = { smem_u32(smB[0]), smem_u32(smB[1]) };

    const int lrow0 = tid >> 2;
    const int lc    = tid & 3;
    const uint32_t loff0 = sw_off(lrow0, lc);
    const uint32_t loff1 = sw_off(lrow0 + 64, lc);

    float accf[2][8][4];
#pragma unroll
    for (int i = 0; i < 2; i++)
#pragma unroll
        for (int j = 0; j < 8; j++)
#pragma unroll
            for (int q = 0; q < 4; q++) accf[i][j][q] = 0.0f;

    const int nk = K >> 5;

    {
        const char* ga0 = (const char*)(Ag + (size_t)lrow0 * K + lc * 8);
        const char* ga1 = (const char*)(Ag + (size_t)(lrow0 + 64) * K + lc * 8);
        const char* gb0 = (const char*)(Bg + (size_t)lrow0 * K + lc * 8);
        const char* gb1 = (const char*)(Bg + (size_t)(lrow0 + 64) * K + lc * 8);
        cp16(sA[0] + loff0, ga0); cp16(sA[0] + loff1, ga1);
        cp16(sB[0] + loff0, gb0); cp16(sB[0] + loff1, gb1);
        cp_commit();
    }

    const int a_row = (lid & 15);
    const int a_cd  = (lid >> 4);
    const int b_row = (lid & 7) + ((lid >> 4) & 1) * 8;
    const int b_cd  = (lid >> 3) & 1;

    for (int kc = 0; kc < nk; kc++) {
        if (kc + 1 < nk) {
            int koff = (kc + 1) * 32;
            int st = (kc + 1) & 1;
            const char* ga0 = (const char*)(Ag + (size_t)lrow0 * K + koff + lc * 8);
            const char* ga1 = (const char*)(Ag + (size_t)(lrow0 + 64) * K + koff + lc * 8);
            const char* gb0 = (const char*)(Bg + (size_t)lrow0 * K + koff + lc * 8);
            const char* gb1 = (const char*)(Bg + (size_t)(lrow0 + 64) * K + koff + lc * 8);
            cp16(sA[st] + loff0, ga0); cp16(sA[st] + loff1, ga1);
            cp16(sB[st] + loff0, gb0); cp16(sB[st] + loff1, gb1);
        }
        cp_commit();
        cp_wait1();
        __syncthreads();

        const uint32_t aT = sA[kc & 1], bT = sB[kc & 1];
#pragma unroll
        for (int ks = 0; ks < 2; ks++) {
            uint32_t afr[2][4];
#pragma unroll
            for (int fm = 0; fm < 2; fm++) {
                int row = warp_m * 32 + fm * 16 + a_row;
                ldsm_x4(afr[fm][0], afr[fm][1], afr[fm][2], afr[fm][3],
                        aT + sw_off(row, 2 * ks + a_cd));
            }
            uint32_t bfr[8][2];
#pragma unroll
            for (int ng = 0; ng < 4; ng++) {
                int row = warp_n * 64 + ng * 16 + b_row;
                uint32_t r0, r1, r2, r3;
                ldsm_x4(r0, r1, r2, r3, bT + sw_off(row, 2 * ks + b_cd));
                bfr[ng * 2][0] = r0;     bfr[ng * 2][1] = r1;
                bfr[ng * 2 + 1][0] = r2; bfr[ng * 2 + 1][1] = r3;
            }
#pragma unroll
            for (int fm = 0; fm < 2; fm++)
#pragma unroll
                for (int fn = 0; fn < 8; fn++)
                    mma_bf16(accf[fm][fn], afr[fm], bfr[fn]);
        }
        __syncthreads();
    }

#pragma unroll
    for (int fm = 0; fm < 2; fm++) {
        int row = m0 + warp_m * 32 + fm * 16 + (lid >> 2);
#pragma unroll
        for (int fn = 0; fn < 8; fn++) {
            int colg = n0 + warp_n * 64 + fn * 8 + (lid & 3) * 2;
            float2 v0 = make_float2(accf[fm][fn][0], accf[fm][fn][1]);
            float2 v1 = make_float2(accf[fm][fn][2], accf[fm][fn][3]);
            if (bias) {
                float b0 = bias[colg], b1 = bias[colg + 1];
                v0.x += b0; v0.y += b1; v1.x += b0; v1.y += b1;
            }
            float* p0 = C + (size_t)row * G3 + colg;
            float* p1 = C + (size_t)(row + 8) * G3 + colg;
            if (acc) {
                float2 o0 = *(const float2*)p0;
                float2 o1 = *(const float2*)p1;
                v0.x += o0.x; v0.y += o0.y; v1.x += o1.x; v1.y += o1.y;
            }
            *(float2*)p0 = v0;
            *(float2*)p1 = v1;
        }
    }
}

// ---------------- tensor-core persistent scan (v3: 64 CTAs) ----------------
// 64 CTAs x 256 thr. CTA cb owns h-cols c0..c0+3 (c0 = 4*cb) -> 12 weight cols
// (padded to 16). Warp-local A fill, resident B fragments (one x4 per kt/half),
// fp32 register carry, REDG + single-poller monotonic barrier.
#define AS_OFF   0
#define BS_OFF   65536
#define PART_OFF 81920
#define PSTR     20                       // part row stride (floats), conflict-free
#define SCAN_SMEM (PART_OFF + 2*64*PSTR*4)

__global__ void __launch_bounds__(SNT, 1)
scan_tc(const float* __restrict__ gi, const __nv_bfloat16* __restrict__ Wsc,
        const float* __restrict__ bhh, const float* __restrict__ tau,
        float* __restrict__ out, int outc0, __nv_bfloat16* __restrict__ a3)
{
    extern __shared__ char sm[];
    const uint32_t as_u = smem_u32(sm + AS_OFF);
    const uint32_t bs_u = smem_u32(sm + BS_OFF);
    float* part = (float*)(sm + PART_OFF);

    const int cb  = blockIdx.x;
    const int tid = threadIdx.x;
    const int wid = tid >> 5, lid = tid & 31;
    const int c0  = cb * 4;
    const int wm  = wid & 3;          // M-tile (16 rows)
    const int khh = wid >> 2;         // k-half

    const int eb  = tid >> 2;         // epilogue batch row (0..63)
    const int ejj = tid & 3;          // epilogue col (0..3)
    const int col = c0 + ejj;

    float bias[3];
#pragma unroll
    for (int g = 0; g < 3; g++) bias[g] = bhh[g * 256 + col];
    const float invt = 1.0f / tau[0];
    float hold1 = 0.0f;               // exact fp32 recurrent carry

    // stationary weights -> smem (one-time): 16 rows x 64 chunks
    for (int i = tid; i < 1024; i += SNT) {
        int n = i >> 6, c = i & 63;
        cp16(bs_u + sw1k(n, c), Wsc + (size_t)cb * 16 * 512 + n * 512 + c * 8);
    }
    cp_commit();
    cp_wait0();
    __syncthreads();

    // resident B fragments: per kt one x4 (16 B-rows = 2 n8-tiles), hi + lo
    const int b_row = (lid & 7) + ((lid >> 4) & 1) * 8;
    const int b_cd  = (lid >> 3) & 1;
    uint32_t bH[8][4], bL[8][4];
#pragma unroll
    for (int ii = 0; ii < 8; ii++) {
        int kt = khh * 8 + ii;
        ldsm_x4(bH[ii][0], bH[ii][1], bH[ii][2], bH[ii][3],
                bs_u + sw1k(b_row, 2 * kt + b_cd));
        ldsm_x4(bL[ii][0], bL[ii][1], bL[ii][2], bL[ii][3],
                bs_u + sw1k(b_row, 2 * (16 + kt) + b_cd));
    }

    // gi register prefetch for t=0 (one col per thread)
    const float* g0 = gi + (size_t)eb * G3 + col;
    float pr = g0[0], pz = g0[256], pn = g0[512];

    const int a_row = wm * 16 + (lid & 15);
    const int a_cd  = lid >> 4;
    const int fl_c  = (lid < 16) ? (khh * 16 + lid) : (32 + khh * 16 + lid - 16);

    for (int t = 0; t < NT; t++) {
        const int cur = t & 1, nxt = cur ^ 1;
        const __nv_bfloat16* hsrc = g_hsplit[cur];

        // prefetch gi for t+1 (independent; hides behind MMA)
        int tnn = (t + 1 < NT) ? t + 1 : t;
        const float* gx = gi + ((size_t)tnn * 64 + eb) * G3 + col;
        float tr = gx[0], tz = gx[256], tn2 = gx[512];

        // warp-local A fill: 16 rows x this lane's chunk
#pragma unroll
        for (int i = 0; i < 16; i++) {
            int row = wm * 16 + i;
            cp16(as_u + sw1k(row, fl_c), hsrc + row * 512 + fl_c * 8);
        }
        cp_commit();
        cp_wait0();
        __syncwarp();

        // MMA: 3 products x 2 n8-tiles x 8 kt = 48 HMMA/warp
        float cf[2][4];
#pragma unroll
        for (int nt = 0; nt < 2; nt++)
#pragma unroll
            for (int q = 0; q < 4; q++) cf[nt][q] = 0.0f;

#pragma unroll
        for (int ii = 0; ii < 8; ii++) {
            int kt = khh * 8 + ii;
            uint32_t aH[4], aL[4];
            ldsm_x4(aH[0], aH[1], aH[2], aH[3], as_u + sw1k(a_row, 2 * kt + a_cd));
            ldsm_x4(aL[0], aL[1], aL[2], aL[3], as_u + sw1k(a_row, 2 * (16 + kt) + a_cd));
            mma_bf16(cf[0], aH, &bH[ii][0]);
            mma_bf16(cf[1], aH, &bH[ii][2]);
            mma_bf16(cf[0], aL, &bH[ii][0]);
            mma_bf16(cf[1], aL, &bH[ii][2]);
            mma_bf16(cf[0], aH, &bL[ii][0]);
            mma_bf16(cf[1], aH, &bL[ii][2]);
        }

        // exchange partials: part[(khh*64 + row)*PSTR + n]
#pragma unroll
        for (int nt = 0; nt < 2; nt++) {
            int r0 = wm * 16 + (lid >> 2);
            int cc = nt * 8 + (lid & 3) * 2;
            *(float2*)&part[(khh * 64 + r0) * PSTR + cc]     = make_float2(cf[nt][0], cf[nt][1]);
            *(float2*)&part[(khh * 64 + r0 + 8) * PSTR + cc] = make_float2(cf[nt][2], cf[nt][3]);
        }
        __syncthreads();

        // gates (one col per thread; register carry + register gi)
        {
            const float* p0 = part + eb * PSTR;
            const float* p1 = part + (64 + eb) * PSTR;
            float sr = p0[ejj]     + p1[ejj];
            float sz = p0[4 + ejj] + p1[4 + ejj];
            float sn = p0[8 + ejj] + p1[8 + ejj];
            float r = sigmoidf_(pr + sr + bias[0]);
            float z = sigmoidf_(pz + sz + bias[1]);
            float n = tanhf_(pn + r * (sn + bias[2]));
            float hc = (1.0f - z) * n + z * hold1;
            float hnew = hold1 + invt * (hc - hold1);
            hold1 = hnew;

            __nv_bfloat16 nh = __float2bfloat16(hnew);
            __nv_bfloat16 nl = __float2bfloat16(hnew - __bfloat162float(nh));
            __nv_bfloat16* hd = g_hsplit[nxt] + eb * 512 + col;
            hd[0]   = nh;
            hd[256] = nl;
            out[((size_t)eb * NT + t) * 512 + outc0 + col] = hnew;
            if (a3) {
                __nv_bfloat16* ad = a3 + ((size_t)t * 64 + eb) * (3 * H) + col;
                ad[0]   = nh;
                ad[256] = nl;
                ad[512] = nh;
            }
        }
        __syncthreads();   // h stores sequenced before tid0's release-arrival

        if (tid == 0) {
            asm volatile("red.release.gpu.global.add.u32 [%0], %1;"
                         :: "l"(&g_cnt), "r"(1u) : "memory");
            unsigned tgt = (unsigned)SNC * (unsigned)(t + 1);
            unsigned v;
            do {
                asm volatile("ld.acquire.gpu.global.u32 %0, [%1];"
                             : "=r"(v) : "l"(&g_cnt) : "memory");
            } while (v < tgt);
        }
        __syncthreads();

        pr = tr; pz = tz; pn = tn2;
    }
}

// ---------------- launch ----------------
extern "C" void kernel_launch(void* const* d_in, const int* in_sizes, int n_in,
                              void* d_out, int out_size) {
    const float* x    = (const float*)d_in[0];
    const float* tau1 = (const float*)d_in[1];
    const float* tau2 = (const float*)d_in[2];
    const float* Wih1 = (const float*)d_in[3];
    const float* Whh1 = (const float*)d_in[4];
    const float* bih1 = (const float*)d_in[5];
    const float* bhh1 = (const float*)d_in[6];
    const float* Wih2 = (const float*)d_in[7];
    const float* Whh2 = (const float*)d_in[8];
    const float* bih2 = (const float*)d_in[9];
    const float* bhh2 = (const float*)d_in[10];
    float* out = (float*)d_out;

    float *gi1, *gi2;
    __nv_bfloat16 *Ab, *A3, *B1, *B2, *B3, *Wr1, *Wr2;
    cudaGetSymbolAddress((void**)&gi1, g_gi1);
    cudaGetSymbolAddress((void**)&gi2, g_gi2);
    cudaGetSymbolAddress((void**)&Ab,  g_Abuf);
    cudaGetSymbolAddress((void**)&A3,  g_A3);
    cudaGetSymbolAddress((void**)&B1,  g_B1);
    cudaGetSymbolAddress((void**)&B2,  g_B2);
    cudaGetSymbolAddress((void**)&B3,  g_B3);
    cudaGetSymbolAddress((void**)&Wr1, g_Wr1);
    cudaGetSymbolAddress((void**)&Wr2, g_Wr2);

    cudaFuncSetAttribute(scan_tc,
                         cudaFuncAttributeMaxDynamicSharedMemorySize, SCAN_SMEM);

    dim3 ggrid(G3 / 128, BT / 128);   // (6, 256)
    int wgrid = (SNC * 16 * 512 + 255) / 256;

    prepA_kernel<<<(int)(((long)BT * D_IN + 255) / 256), 256>>>(x, Ab);        // 0
    {
        long tot = 2L * G3 * D_IN + (long)G3 * H;
        prepB_all<<<(int)((tot + 255) / 256), 256>>>(
            Wih1, Wih2, Wih2 + (size_t)D_IN * G3, B1, B2, B3);                 // 1
    }
    prepWhh<<<wgrid, 256>>>(Whh1, Wr1);                                        // 2 (+init)
    gemm_mma<<<ggrid, 256>>>(Ab, B1, 3 * D_IN, bih1, gi1, 0);                  // 3
    scan_tc<<<SNC, SNT, SCAN_SMEM>>>(gi1, Wr1, bhh1, tau1, out, 0, A3);        // 4
    prepWhh<<<wgrid, 256>>>(Whh2, Wr2);                                        // 5 (+re-init)
    gemm_mma<<<ggrid, 256>>>(Ab, B2, 3 * D_IN, bih2, gi2, 0);                  // 6
    gemm_mma<<<ggrid, 256>>>(A3, B3, 3 * H, nullptr, gi2, 1);                  // 7
    scan_tc<<<SNC, SNT, SCAN_SMEM>>>(gi2, Wr2, bhh2, tau2, out, 256, nullptr); // 8
}